// round 9
// baseline (speedup 1.0000x reference)
#include <cuda_runtime.h>

// Problem constants
#define Bq 16
#define Tq 1024
#define Cq 768
#define Mq (Bq*Tq)          // 16384
#define NBC (Bq*Cq)         // 12288
#define Ls 16               // chunk length
#define Ss 64               // num chunks (Ls*Ss == Tq)
#define WN (Cq*Cq)          // 589824 weight elements

// -------- device scratch (static, no allocations) --------
__device__ float g_k [12582912];   // holds exp(k) after k-GEMM
__device__ float g_v [12582912];
__device__ float g_sr[12582912];
__device__ float g_y [12582912];
__device__ float g_w [4*WN];       // tf32-prerounded weights: k,v,r,o
// chunk carries: [Bq][Ss][Cq], packed as float2 (num, den)
#define CHN (Bq*Ss*Cq)
__device__ float2 g_cFF [CHN];     // chunk-local forward (num, den)
__device__ float2 g_cBB [CHN];     // chunk-local backward (num, den)
__device__ float2 g_FinP[CHN];     // incoming forward carry (num, den)
__device__ float2 g_BinP[CHN];     // incoming backward carry (num, den)

// -------- tf32 / async helpers --------
__device__ __forceinline__ float to_tf32(float f){
    unsigned u;
    asm("cvt.rna.tf32.f32 %0, %1;" : "=r"(u) : "f"(f));
    return __uint_as_float(u);
}

__device__ __forceinline__ void cp_async16(float* smem_dst, const float* gmem_src){
    unsigned s = (unsigned)__cvta_generic_to_shared(smem_dst);
    asm volatile("cp.async.ca.shared.global [%0], [%1], 16;\n" :: "r"(s), "l"(gmem_src));
}
#define CP_COMMIT() asm volatile("cp.async.commit_group;\n" ::: "memory")
#define CP_WAIT0()  asm volatile("cp.async.wait_group 0;\n" ::: "memory")

__device__ __forceinline__ void mma8(float d[4], const float a[4], const float b[2]){
    const unsigned* A  = reinterpret_cast<const unsigned*>(a);
    const unsigned* Bb = reinterpret_cast<const unsigned*>(b);
    asm volatile(
      "mma.sync.aligned.m16n8k8.row.col.f32.tf32.tf32.f32 "
      "{%0,%1,%2,%3}, {%4,%5,%6,%7}, {%8,%9}, {%0,%1,%2,%3};\n"
      : "+f"(d[0]), "+f"(d[1]), "+f"(d[2]), "+f"(d[3])
      : "r"(A[0]), "r"(A[1]), "r"(A[2]), "r"(A[3]), "r"(Bb[0]), "r"(Bb[1]));
}

// -------- weight prep: RNA-round all 4 weight matrices to tf32 --------
__global__ void prep_w(const float* __restrict__ wk, const float* __restrict__ wv,
                       const float* __restrict__ wr, const float* __restrict__ wo)
{
    int i = blockIdx.x * blockDim.x + threadIdx.x;
    if (i >= WN) return;
    g_w[i       ] = to_tf32(wk[i]);
    g_w[i +   WN] = to_tf32(wv[i]);
    g_w[i + 2*WN] = to_tf32(wr[i]);
    g_w[i + 3*WN] = to_tf32(wo[i]);
}

// -------- GEMM: C[m,n] = sum_k A[m,k] * W[n,k] --------
// XOR-swizzled smem layout, pitch 32 floats: idx = row*32 + ((col4 ^ (row&7))<<2) + col&3.
#define BM 128
#define BN 128
#define BK 32
#define NKI (Cq/BK)   // 24

__device__ __forceinline__ int sw_idx(int row, int col4, int c){
    return row*32 + ((col4 ^ (row & 7)) << 2) + c;
}

template<bool MIXED>
__global__ __launch_bounds__(256, 2) void gemm_tf32(
    const float* __restrict__ x,
    const float* __restrict__ mk, const float* __restrict__ mv, const float* __restrict__ mr,
    float* __restrict__ Cext)
{
    __shared__ float As[BM*32];        // single buffer
    __shared__ float Bs[2*BN*32];      // double buffer  -> total 48KB

    const float* W;
    const float* mix = nullptr;
    float* Cout;
    const float* Ap;
    int z = MIXED ? blockIdx.z : 0;
    if (MIXED) {
        W    = g_w + (size_t)z*WN;
        mix  = (z==0) ? mk : (z==1) ? mv : mr;
        Cout = (z==0) ? g_k : (z==1) ? g_v : g_sr;
        Ap   = x;
    } else {
        W = g_w + (size_t)3*WN; Cout = Cext; Ap = g_y;
    }

    const int m0 = blockIdx.y * BM;
    const int n0 = blockIdx.x * BN;
    const int tid  = threadIdx.x;
    const int lane = tid & 31;
    const int wid  = tid >> 5;
    const int wm = wid & 3;
    const int wn = wid >> 2;
    const int grp8 = lane >> 2;
    const int c4   = lane & 3;
    const int lrow = tid >> 3;        // 0..31
    const int lk4  = tid & 7;         // col4 index 0..7
    const int lk   = lk4 << 2;        // 0,4,..,28

    float4 aR[4];

    auto loadA = [&](int kt){
        #pragma unroll
        for (int p=0;p<4;p++){
            int row = p*32 + lrow;
            int m = m0 + row;
            int kk = kt + lk;
            float4 a4;
            if (MIXED) {
                int t  = m & (Tq-1);
                int bb = m >> 10;
                int grp = kk / 192;
                int wq = t & 31, hq = t >> 5;
                int tt; bool valid;
                if      (grp==0) { tt = t-1;  valid = (wq > 0);  }
                else if (grp==1) { tt = t+1;  valid = (wq < 31); }
                else if (grp==2) { tt = t-32; valid = (hq > 0);  }
                else             { tt = t+32; valid = (hq < 31); }
                float4 xv = *reinterpret_cast<const float4*>(Ap + (size_t)m*Cq + kk);
                float4 xs = make_float4(0.f,0.f,0.f,0.f);
                if (valid)
                    xs = *reinterpret_cast<const float4*>(Ap + ((size_t)(bb<<10) + tt)*Cq + kk);
                float4 mx = *reinterpret_cast<const float4*>(mix + kk);
                a4.x = mx.x*(xv.x - xs.x) + xs.x;
                a4.y = mx.y*(xv.y - xs.y) + xs.y;
                a4.z = mx.z*(xv.z - xs.z) + xs.z;
                a4.w = mx.w*(xv.w - xs.w) + xs.w;
            } else {
                a4 = *reinterpret_cast<const float4*>(Ap + (size_t)m*Cq + kk);
            }
            aR[p].x = to_tf32(a4.x); aR[p].y = to_tf32(a4.y);
            aR[p].z = to_tf32(a4.z); aR[p].w = to_tf32(a4.w);
        }
    };
    auto storeA = [&](){
        #pragma unroll
        for (int p=0;p<4;p++){
            int row = p*32 + lrow;
            *reinterpret_cast<float4*>(&As[sw_idx(row, lk4, 0)]) = aR[p];
        }
    };
    auto loadB = [&](int buf, int kt){
        float* base = Bs + buf*BN*32;
        #pragma unroll
        for (int p=0;p<4;p++){
            int n = p*32 + lrow;
            cp_async16(base + sw_idx(n, lk4, 0), W + (size_t)(n0+n)*Cq + kt + lk);
        }
    };

    float acc[2][8][4];
    #pragma unroll
    for (int i=0;i<2;i++)
      #pragma unroll
      for (int j=0;j<8;j++)
        #pragma unroll
        for (int q=0;q<4;q++) acc[i][j][q] = 0.f;

    // prologue
    loadA(0);
    loadB(0, 0); CP_COMMIT();
    storeA();
    CP_WAIT0();
    __syncthreads();

    for (int it = 0; it < NKI; it++){
        int cur = it & 1;
        if (it + 1 < NKI){
            loadB(cur^1, (it+1)*BK); CP_COMMIT();
            loadA((it+1)*BK);
        }

        const float* Bb = Bs + cur*BN*32;

        // ---- register-pipelined fragment loop over ks ----
        float bfr[2][8][2];
        {   // preload B frags for ks=0
            #pragma unroll
            for (int j=0;j<8;j++){
                int n = wn*64 + j*8 + grp8;
                bfr[0][j][0] = Bb[sw_idx(n, 0, c4)];
                bfr[0][j][1] = Bb[sw_idx(n, 1, c4)];
            }
        }
        #pragma unroll
        for (int ks=0; ks<4; ks++){
            int stage = ks & 1;
            if (ks < 3){
                int kb4n = (ks+1)*2;
                #pragma unroll
                for (int j=0;j<8;j++){
                    int n = wn*64 + j*8 + grp8;
                    bfr[stage^1][j][0] = Bb[sw_idx(n, kb4n,   c4)];
                    bfr[stage^1][j][1] = Bb[sw_idx(n, kb4n+1, c4)];
                }
            }
            int kb4 = ks*2;
            float af[2][4];
            #pragma unroll
            for (int i=0;i<2;i++){
                int r = wm*32 + i*16;
                af[i][0] = As[sw_idx(r+grp8,   kb4,   c4)];
                af[i][1] = As[sw_idx(r+grp8+8, kb4,   c4)];
                af[i][2] = As[sw_idx(r+grp8,   kb4+1, c4)];
                af[i][3] = As[sw_idx(r+grp8+8, kb4+1, c4)];
            }
            #pragma unroll
            for (int i=0;i<2;i++)
                #pragma unroll
                for (int j=0;j<8;j++)
                    mma8(acc[i][j], af[i], bfr[stage][j]);
        }

        __syncthreads();
        if (it + 1 < NKI){
            storeA();
            CP_WAIT0();
        }
        __syncthreads();
    }

    #pragma unroll
    for (int i=0;i<2;i++){
        int r = m0 + wm*32 + i*16 + grp8;
        #pragma unroll
        for (int j=0;j<8;j++){
            int col = n0 + wn*64 + j*8 + 2*c4;
            float v0 = acc[i][j][0], v1 = acc[i][j][1];
            float v2 = acc[i][j][2], v3 = acc[i][j][3];
            if (MIXED && z == 0){   // store exp(k) directly
                v0 = __expf(v0); v1 = __expf(v1);
                v2 = __expf(v2); v3 = __expf(v3);
            }
            if (MIXED && z == 2){
                v0 = 1.f/(1.f+__expf(-v0)); v1 = 1.f/(1.f+__expf(-v1));
                v2 = 1.f/(1.f+__expf(-v2)); v3 = 1.f/(1.f+__expf(-v3));
            }
            *reinterpret_cast<float2*>(Cout + (size_t)r*Cq + col)     = make_float2(v0, v1);
            *reinterpret_cast<float2*>(Cout + (size_t)(r+8)*Cq + col) = make_float2(v2, v3);
        }
    }
}

// ================= chunked bi_wkv scan (g_k holds exp(k)) =================
__device__ __forceinline__ float get_ew(const float* decay, int c){
    float w = decay[c] * (1.0f / (float)Tq);
    return __expf(-__expf(w));
}

// Phase A: per-(b,s,c) chunk-local weighted sums. grid (Ss, Bq), block 768
__global__ __launch_bounds__(768) void wkv_chunk(const float* __restrict__ decay)
{
    int s = blockIdx.x, b = blockIdx.y, c = threadIdx.x;
    float ew = get_ew(decay, c);
    size_t base = ((size_t)b*Tq + s*Ls)*Cq + c;

    float fF=0.f, dF=0.f, fB=0.f, dB=0.f, pw=1.f;
    #pragma unroll
    for (int i=0;i<Ls;i++){
        size_t idx = base + (size_t)i*Cq;
        float ek = g_k[idx], vv = g_v[idx];
        float ekv = ek*vv;
        fF = fmaf(ew, fF, ekv);
        dF = fmaf(ew, dF, ek);
        fB = fmaf(pw, ekv, fB);
        dB = fmaf(pw, ek, dB);
        pw *= ew;
    }
    size_t ci = ((size_t)b*Ss + s)*Cq + c;
    g_cFF[ci] = make_float2(fF, dF);
    g_cBB[ci] = make_float2(fB, dB);
}

// Phase B: scan the Ss chunk carries per (b,c). gridDim.y = direction.
__global__ __launch_bounds__(256) void wkv_carry(const float* __restrict__ decay)
{
    int gid = blockIdx.x * blockDim.x + threadIdx.x;
    if (gid >= NBC) return;
    int b = gid / Cq, c = gid % Cq;
    float ew = get_ew(decay, c);
    float e2 = ew*ew, e4 = e2*e2, e8 = e4*e4, ewL = e8*e8;  // ew^16
    size_t base = (size_t)b*Ss*Cq + c;

    if (blockIdx.y == 0){
        float fin=0.f, fdin=0.f;
        #pragma unroll 8
        for (int s=0;s<Ss;s++){
            size_t ci = base + (size_t)s*Cq;
            float2 cf = g_cFF[ci];
            g_FinP[ci] = make_float2(fin, fdin);
            fin  = fmaf(ewL, fin,  cf.x);
            fdin = fmaf(ewL, fdin, cf.y);
        }
    } else {
        float bin=0.f, bdin=0.f;
        #pragma unroll 8
        for (int s=Ss-1;s>=0;s--){
            size_t ci = base + (size_t)s*Cq;
            float2 cb = g_cBB[ci];
            g_BinP[ci] = make_float2(bin, bdin);
            bin  = fmaf(ewL, bin,  cb.x);
            bdin = fmaf(ewL, bdin, cb.y);
        }
    }
}

// Phase C: apply carries, produce y = sr * wkv. grid (Ss, Bq*3), block 256
__global__ __launch_bounds__(256) void wkv_apply(const float* __restrict__ decay,
                                                 const float* __restrict__ first)
{
    int s = blockIdx.x;
    int b = blockIdx.y / 3;
    int c = (blockIdx.y % 3)*256 + threadIdx.x;
    float ew = get_ew(decay, c);
    float expu = __expf(first[c] * (1.0f / (float)Tq));
    size_t base = ((size_t)b*Tq + s*Ls)*Cq + c;
    size_t ci   = ((size_t)b*Ss + s)*Cq + c;

    // backward micro-scan (exclusive per element)
    float bnA[Ls], bdA[Ls];
    float2 bc = g_BinP[ci];
    float bn = bc.x, bd = bc.y;
    #pragma unroll
    for (int i=Ls-1;i>=0;i--){
        size_t idx = base + (size_t)i*Cq;
        float ek = g_k[idx], vv = g_v[idx];
        bnA[i] = bn; bdA[i] = bd;
        bn = fmaf(ew, bn, ek*vv);
        bd = fmaf(ew, bd, ek);
    }

    // forward micro-scan + combine + sr multiply
    float2 fc = g_FinP[ci];
    float fn = fc.x, fd = fc.y;
    #pragma unroll
    for (int i=0;i<Ls;i++){
        size_t idx = base + (size_t)i*Cq;
        float ek = g_k[idx], vv = g_v[idx];
        float eu = expu * ek;
        float out = (fn + bnA[i] + eu*vv) / (fd + bdA[i] + eu);
        g_y[idx] = g_sr[idx] * out;
        fn = fmaf(ew, fn, ek*vv);
        fd = fmaf(ew, fd, ek);
    }
}

extern "C" void kernel_launch(void* const* d_in, const int* in_sizes, int n_in,
                              void* d_out, int out_size)
{
    const float* x       = (const float*)d_in[0];
    const float* key_w   = (const float*)d_in[1];
    const float* value_w = (const float*)d_in[2];
    const float* recep_w = (const float*)d_in[3];
    const float* out_w   = (const float*)d_in[4];
    const float* decay   = (const float*)d_in[5];
    const float* first   = (const float*)d_in[6];
    const float* mk      = (const float*)d_in[7];
    const float* mv      = (const float*)d_in[8];
    const float* mr      = (const float*)d_in[9];
    float* out = (float*)d_out;

    // 0) pre-round weights to tf32
    prep_w<<<(WN+255)/256, 256>>>(key_w, value_w, recep_w, out_w);

    // 1) exp(k), v, sr
    dim3 grid1(Cq/BN, Mq/BM, 3);
    gemm_tf32<true><<<grid1, 256>>>(x, mk, mv, mr, nullptr);

    // 2) chunked bidirectional scan
    wkv_chunk<<<dim3(Ss, Bq), 768>>>(decay);
    wkv_carry<<<dim3(NBC/256, 2), 256>>>(decay);
    wkv_apply<<<dim3(Ss, Bq*3), 256>>>(decay, first);

    // 3) out = (sr * rwkv) @ output_w^T
    dim3 grid2(Cq/BN, Mq/BM, 1);
    gemm_tf32<false><<<grid2, 256>>>(nullptr, nullptr, nullptr, nullptr, out);
}

// round 11
// speedup vs baseline: 1.6704x; 1.6704x over previous
#include <cuda_runtime.h>
#include <cuda_fp16.h>
#include <cstdint>

// Problem constants
#define Bq 16
#define Tq 1024
#define Cq 768
#define Mq (Bq*Tq)          // 16384
#define NBC (Bq*Cq)         // 12288
#define Ls 16               // chunk length
#define Ss 64               // num chunks (Ls*Ss == Tq)
#define WN (Cq*Cq)          // 589824 weight elements

// -------- device scratch (static, no allocations) --------
__device__ float g_k [12582912];   // holds exp(k) after k-GEMM
__device__ float g_v [12582912];
__device__ float g_sr[12582912];
__device__ float g_y [12582912];
__device__ __half g_wh[4*WN];      // fp16 weights: k,v,r,o
// chunk carries: [Bq][Ss][Cq], packed as float2 (num, den)
#define CHN (Bq*Ss*Cq)
__device__ float2 g_cFF [CHN];
__device__ float2 g_cBB [CHN];
__device__ float2 g_FinP[CHN];
__device__ float2 g_BinP[CHN];

// -------- helpers --------
__device__ __forceinline__ void cp_async16(uint32_t smem_dst, const void* gmem_src){
    asm volatile("cp.async.ca.shared.global [%0], [%1], 16;\n" :: "r"(smem_dst), "l"(gmem_src));
}
#define CP_COMMIT() asm volatile("cp.async.commit_group;\n" ::: "memory")
#define CP_WAIT0()  asm volatile("cp.async.wait_group 0;\n" ::: "memory")

__device__ __forceinline__ void ldmx4(unsigned &r0, unsigned &r1, unsigned &r2, unsigned &r3,
                                      uint32_t addr){
    asm volatile("ldmatrix.sync.aligned.m8n8.x4.shared.b16 {%0,%1,%2,%3}, [%4];"
      : "=r"(r0), "=r"(r1), "=r"(r2), "=r"(r3) : "r"(addr));
}

__device__ __forceinline__ void mma16(float d[4], const unsigned a[4], const unsigned b[2]){
    asm volatile(
      "mma.sync.aligned.m16n8k16.row.col.f32.f16.f16.f32 "
      "{%0,%1,%2,%3}, {%4,%5,%6,%7}, {%8,%9}, {%0,%1,%2,%3};\n"
      : "+f"(d[0]), "+f"(d[1]), "+f"(d[2]), "+f"(d[3])
      : "r"(a[0]), "r"(a[1]), "r"(a[2]), "r"(a[3]), "r"(b[0]), "r"(b[1]));
}

__device__ __forceinline__ unsigned pack2(float a, float b){
    __half2 h = __floats2half2_rn(a, b);
    return *reinterpret_cast<unsigned*>(&h);
}

// -------- weight prep: convert all 4 weight matrices to fp16 --------
__global__ void prep_w(const float* __restrict__ wk, const float* __restrict__ wv,
                       const float* __restrict__ wr, const float* __restrict__ wo)
{
    int i = blockIdx.x * blockDim.x + threadIdx.x;
    if (i >= WN) return;
    g_wh[i       ] = __float2half_rn(wk[i]);
    g_wh[i +   WN] = __float2half_rn(wv[i]);
    g_wh[i + 2*WN] = __float2half_rn(wr[i]);
    g_wh[i + 3*WN] = __float2half_rn(wo[i]);
}

// -------- GEMM: C[m,n] = sum_k A[m,k] * W[n,k], fp16 m16n8k16 --------
// smem tiles: 128 rows x 32 halfs, row pitch 40 halfs (80B). Row bank base =
// row*20 mod 32 cycles through 8 distinct 16B-aligned offsets -> ldmatrix
// row-gather is conflict-free without XOR swizzling.
#define BM 128
#define BN 128
#define BK 32
#define NKI (Cq/BK)     // 24
#define PITCH 40        // halfs per row (80B)
#define TILE_H (BM*PITCH)   // 5120 halfs = 10240B per buffer

template<bool MIXED>
__global__ __launch_bounds__(256, 2) void gemm_fp16(
    const float* __restrict__ x,
    const float* __restrict__ mk, const float* __restrict__ mv, const float* __restrict__ mr,
    float* __restrict__ Cext)
{
    __shared__ __align__(16) __half smA[2][TILE_H];
    __shared__ __align__(16) __half smB[2][TILE_H];

    const __half* W;
    const float* mix = nullptr;
    float* Cout;
    const float* Ap;
    int z = MIXED ? blockIdx.z : 0;
    if (MIXED) {
        W    = g_wh + (size_t)z*WN;
        mix  = (z==0) ? mk : (z==1) ? mv : mr;
        Cout = (z==0) ? g_k : (z==1) ? g_v : g_sr;
        Ap   = x;
    } else {
        W = g_wh + (size_t)3*WN; Cout = Cext; Ap = g_y;
    }

    const int m0 = blockIdx.y * BM;
    const int n0 = blockIdx.x * BN;
    const int tid  = threadIdx.x;
    const int lane = tid & 31;
    const int wid  = tid >> 5;
    const int wm = wid & 3;        // 4 warps along M (32 rows each)
    const int wn = wid >> 2;       // 2 warps along N (64 cols each)
    const int grp8 = lane >> 2;
    const int c4   = lane & 3;

    const uint32_t uA = (uint32_t)__cvta_generic_to_shared(&smA[0][0]);
    const uint32_t uB = (uint32_t)__cvta_generic_to_shared(&smB[0][0]);

    // ldmatrix per-lane address bases (byte offsets within a buffer)
    const int q = lane >> 3, rr = lane & 7;
    // A: matrices {m-lo,k-lo},{m-hi,k-lo},{m-lo,k-hi},{m-hi,k-hi}
    const uint32_t aOff = (uint32_t)((wm*32 + ((q&1)<<3) + rr)*80 + (q>>1)*16);
    // B: matrices {j,k-lo},{j,k-hi},{j+1,k-lo},{j+1,k-hi}
    const uint32_t bOff = (uint32_t)((wn*64 + ((q>>1)<<3) + rr)*80 + (q&1)*16);

    // ---- A tile loader: global -> regs (fused q_shift + mix + fp16 pack) ----
    uint4 aU[2];
    auto loadA = [&](int kt){
        #pragma unroll
        for (int p=0;p<2;p++){
            int linear = p*256 + tid;
            int row = linear >> 2, seg = linear & 3;
            int m = m0 + row;
            int kk = kt + seg*8;
            float4 v0, v1;
            if (MIXED) {
                int t  = m & (Tq-1);
                int bb = m >> 10;
                int grp = kk / 192;
                int wq = t & 31, hq = t >> 5;
                int tt; bool valid;
                if      (grp==0) { tt = t-1;  valid = (wq > 0);  }
                else if (grp==1) { tt = t+1;  valid = (wq < 31); }
                else if (grp==2) { tt = t-32; valid = (hq > 0);  }
                else             { tt = t+32; valid = (hq < 31); }
                const float* xb = Ap + (size_t)m*Cq + kk;
                float4 xv0 = *reinterpret_cast<const float4*>(xb);
                float4 xv1 = *reinterpret_cast<const float4*>(xb + 4);
                float4 xs0 = make_float4(0.f,0.f,0.f,0.f);
                float4 xs1 = make_float4(0.f,0.f,0.f,0.f);
                if (valid){
                    const float* sb = Ap + ((size_t)(bb<<10) + tt)*Cq + kk;
                    xs0 = *reinterpret_cast<const float4*>(sb);
                    xs1 = *reinterpret_cast<const float4*>(sb + 4);
                }
                float4 mx0 = *reinterpret_cast<const float4*>(mix + kk);
                float4 mx1 = *reinterpret_cast<const float4*>(mix + kk + 4);
                v0.x = mx0.x*(xv0.x - xs0.x) + xs0.x;
                v0.y = mx0.y*(xv0.y - xs0.y) + xs0.y;
                v0.z = mx0.z*(xv0.z - xs0.z) + xs0.z;
                v0.w = mx0.w*(xv0.w - xs0.w) + xs0.w;
                v1.x = mx1.x*(xv1.x - xs1.x) + xs1.x;
                v1.y = mx1.y*(xv1.y - xs1.y) + xs1.y;
                v1.z = mx1.z*(xv1.z - xs1.z) + xs1.z;
                v1.w = mx1.w*(xv1.w - xs1.w) + xs1.w;
            } else {
                const float* yb = Ap + (size_t)m*Cq + kk;
                v0 = *reinterpret_cast<const float4*>(yb);
                v1 = *reinterpret_cast<const float4*>(yb + 4);
            }
            aU[p].x = pack2(v0.x, v0.y);
            aU[p].y = pack2(v0.z, v0.w);
            aU[p].z = pack2(v1.x, v1.y);
            aU[p].w = pack2(v1.z, v1.w);
        }
    };
    auto storeA = [&](int buf){
        #pragma unroll
        for (int p=0;p<2;p++){
            int linear = p*256 + tid;
            int row = linear >> 2, seg = linear & 3;
            *reinterpret_cast<uint4*>(&smA[buf][row*PITCH + seg*8]) = aU[p];
        }
    };
    auto loadB = [&](int buf, int kt){
        uint32_t base = uB + buf*(TILE_H*2);
        #pragma unroll
        for (int p=0;p<2;p++){
            int linear = p*256 + tid;
            int row = linear >> 2, seg = linear & 3;
            cp_async16(base + (uint32_t)(row*80 + seg*16),
                       W + (size_t)(n0+row)*Cq + kt + seg*8);
        }
    };

    float acc[2][8][4];
    #pragma unroll
    for (int i=0;i<2;i++)
      #pragma unroll
      for (int j=0;j<8;j++)
        #pragma unroll
        for (int qd=0;qd<4;qd++) acc[i][j][qd] = 0.f;

    // prologue
    loadA(0);
    loadB(0, 0); CP_COMMIT();
    storeA(0);
    CP_WAIT0();
    __syncthreads();

    for (int it = 0; it < NKI; it++){
        int cur = it & 1;
        if (it + 1 < NKI){
            loadB(cur^1, (it+1)*BK); CP_COMMIT();
            loadA((it+1)*BK);
        }

        uint32_t aBuf = uA + cur*(TILE_H*2);
        uint32_t bBuf = uB + cur*(TILE_H*2);
        #pragma unroll
        for (int ks=0; ks<2; ks++){
            unsigned afr[2][4];
            #pragma unroll
            for (int i=0;i<2;i++)
                ldmx4(afr[i][0], afr[i][1], afr[i][2], afr[i][3],
                      aBuf + aOff + (uint32_t)(i*1280 + ks*32));
            unsigned bfr[8][2];
            #pragma unroll
            for (int jp=0;jp<4;jp++)
                ldmx4(bfr[2*jp][0], bfr[2*jp][1], bfr[2*jp+1][0], bfr[2*jp+1][1],
                      bBuf + bOff + (uint32_t)(jp*1280 + ks*32));
            #pragma unroll
            for (int i=0;i<2;i++)
                #pragma unroll
                for (int j=0;j<8;j++)
                    mma16(acc[i][j], afr[i], bfr[j]);
        }

        if (it + 1 < NKI){
            storeA(cur^1);
            CP_WAIT0();
        }
        __syncthreads();
    }

    // ---- epilogue (same D layout as m16n8k8) ----
    #pragma unroll
    for (int i=0;i<2;i++){
        int r = m0 + wm*32 + i*16 + grp8;
        #pragma unroll
        for (int j=0;j<8;j++){
            int col = n0 + wn*64 + j*8 + 2*c4;
            float v0 = acc[i][j][0], v1 = acc[i][j][1];
            float v2 = acc[i][j][2], v3 = acc[i][j][3];
            if (MIXED && z == 0){   // store exp(k) directly
                v0 = __expf(v0); v1 = __expf(v1);
                v2 = __expf(v2); v3 = __expf(v3);
            }
            if (MIXED && z == 2){
                v0 = 1.f/(1.f+__expf(-v0)); v1 = 1.f/(1.f+__expf(-v1));
                v2 = 1.f/(1.f+__expf(-v2)); v3 = 1.f/(1.f+__expf(-v3));
            }
            *reinterpret_cast<float2*>(Cout + (size_t)r*Cq + col)     = make_float2(v0, v1);
            *reinterpret_cast<float2*>(Cout + (size_t)(r+8)*Cq + col) = make_float2(v2, v3);
        }
    }
}

// ================= chunked bi_wkv scan (g_k holds exp(k)) =================
__device__ __forceinline__ float get_ew(const float* decay, int c){
    float w = decay[c] * (1.0f / (float)Tq);
    return __expf(-__expf(w));
}

__global__ __launch_bounds__(768) void wkv_chunk(const float* __restrict__ decay)
{
    int s = blockIdx.x, b = blockIdx.y, c = threadIdx.x;
    float ew = get_ew(decay, c);
    size_t base = ((size_t)b*Tq + s*Ls)*Cq + c;

    float fF=0.f, dF=0.f, fB=0.f, dB=0.f, pw=1.f;
    #pragma unroll
    for (int i=0;i<Ls;i++){
        size_t idx = base + (size_t)i*Cq;
        float ek = g_k[idx], vv = g_v[idx];
        float ekv = ek*vv;
        fF = fmaf(ew, fF, ekv);
        dF = fmaf(ew, dF, ek);
        fB = fmaf(pw, ekv, fB);
        dB = fmaf(pw, ek, dB);
        pw *= ew;
    }
    size_t ci = ((size_t)b*Ss + s)*Cq + c;
    g_cFF[ci] = make_float2(fF, dF);
    g_cBB[ci] = make_float2(fB, dB);
}

__global__ __launch_bounds__(256) void wkv_carry(const float* __restrict__ decay)
{
    int gid = blockIdx.x * blockDim.x + threadIdx.x;
    if (gid >= NBC) return;
    int b = gid / Cq, c = gid % Cq;
    float ew = get_ew(decay, c);
    float e2 = ew*ew, e4 = e2*e2, e8 = e4*e4, ewL = e8*e8;  // ew^16
    size_t base = (size_t)b*Ss*Cq + c;

    if (blockIdx.y == 0){
        float fin=0.f, fdin=0.f;
        #pragma unroll 8
        for (int s=0;s<Ss;s++){
            size_t ci = base + (size_t)s*Cq;
            float2 cf = g_cFF[ci];
            g_FinP[ci] = make_float2(fin, fdin);
            fin  = fmaf(ewL, fin,  cf.x);
            fdin = fmaf(ewL, fdin, cf.y);
        }
    } else {
        float bin=0.f, bdin=0.f;
        #pragma unroll 8
        for (int s=Ss-1;s>=0;s--){
            size_t ci = base + (size_t)s*Cq;
            float2 cb = g_cBB[ci];
            g_BinP[ci] = make_float2(bin, bdin);
            bin  = fmaf(ewL, bin,  cb.x);
            bdin = fmaf(ewL, bdin, cb.y);
        }
    }
}

__global__ __launch_bounds__(256) void wkv_apply(const float* __restrict__ decay,
                                                 const float* __restrict__ first)
{
    int s = blockIdx.x;
    int b = blockIdx.y / 3;
    int c = (blockIdx.y % 3)*256 + threadIdx.x;
    float ew = get_ew(decay, c);
    float expu = __expf(first[c] * (1.0f / (float)Tq));
    size_t base = ((size_t)b*Tq + s*Ls)*Cq + c;
    size_t ci   = ((size_t)b*Ss + s)*Cq + c;

    float bnA[Ls], bdA[Ls];
    float2 bc = g_BinP[ci];
    float bn = bc.x, bd = bc.y;
    #pragma unroll
    for (int i=Ls-1;i>=0;i--){
        size_t idx = base + (size_t)i*Cq;
        float ek = g_k[idx], vv = g_v[idx];
        bnA[i] = bn; bdA[i] = bd;
        bn = fmaf(ew, bn, ek*vv);
        bd = fmaf(ew, bd, ek);
    }

    float2 fc = g_FinP[ci];
    float fn = fc.x, fd = fc.y;
    #pragma unroll
    for (int i=0;i<Ls;i++){
        size_t idx = base + (size_t)i*Cq;
        float ek = g_k[idx], vv = g_v[idx];
        float eu = expu * ek;
        float out = (fn + bnA[i] + eu*vv) / (fd + bdA[i] + eu);
        g_y[idx] = g_sr[idx] * out;
        fn = fmaf(ew, fn, ek*vv);
        fd = fmaf(ew, fd, ek);
    }
}

extern "C" void kernel_launch(void* const* d_in, const int* in_sizes, int n_in,
                              void* d_out, int out_size)
{
    const float* x       = (const float*)d_in[0];
    const float* key_w   = (const float*)d_in[1];
    const float* value_w = (const float*)d_in[2];
    const float* recep_w = (const float*)d_in[3];
    const float* out_w   = (const float*)d_in[4];
    const float* decay   = (const float*)d_in[5];
    const float* first   = (const float*)d_in[6];
    const float* mk      = (const float*)d_in[7];
    const float* mv      = (const float*)d_in[8];
    const float* mr      = (const float*)d_in[9];
    float* out = (float*)d_out;

    // 0) convert weights to fp16
    prep_w<<<(WN+255)/256, 256>>>(key_w, value_w, recep_w, out_w);

    // 1) exp(k), v, sr
    dim3 grid1(Cq/BN, Mq/BM, 3);
    gemm_fp16<true><<<grid1, 256>>>(x, mk, mv, mr, nullptr);

    // 2) chunked bidirectional scan
    wkv_chunk<<<dim3(Ss, Bq), 768>>>(decay);
    wkv_carry<<<dim3(NBC/256, 2), 256>>>(decay);
    wkv_apply<<<dim3(Ss, Bq*3), 256>>>(decay, first);

    // 3) out = (sr * rwkv) @ output_w^T
    dim3 grid2(Cq/BN, Mq/BM, 1);
    gemm_fp16<false><<<grid2, 256>>>(nullptr, nullptr, nullptr, nullptr, out);
}

// round 14
// speedup vs baseline: 1.7004x; 1.0179x over previous
#include <cuda_runtime.h>
#include <cuda_fp16.h>
#include <cstdint>

// Problem constants
#define Bq 16
#define Tq 1024
#define Cq 768
#define Mq (Bq*Tq)          // 16384
#define NBC (Bq*Cq)         // 12288
#define Ls 16               // chunk length
#define Ss 64               // num chunks (Ls*Ss == Tq)
#define WN (Cq*Cq)          // 589824 weight elements
#define CPAIR (Bq*Ss*(Cq/2))   // channel-pair carry count

// -------- device scratch (static, no allocations) --------
__device__ float g_k [12582912];   // holds exp(k) after k-GEMM
__device__ float g_v [12582912];
__device__ float g_sr[12582912];
__device__ float g_y [12582912];
__device__ __half g_wh[4*WN];      // fp16 weights: k,v,r,o
// carries packed per channel-pair: (num0, den0, num1, den1)
__device__ float4 g_cFP[CPAIR];    // chunk-local forward
__device__ float4 g_cBP[CPAIR];    // chunk-local backward
__device__ float4 g_FiP[CPAIR];    // incoming forward carry (exclusive)
__device__ float4 g_BiP[CPAIR];    // incoming backward carry (exclusive)

// -------- helpers --------
__device__ __forceinline__ void cp_async16(uint32_t smem_dst, const void* gmem_src){
    asm volatile("cp.async.ca.shared.global [%0], [%1], 16;\n" :: "r"(smem_dst), "l"(gmem_src));
}
#define CP_COMMIT() asm volatile("cp.async.commit_group;\n" ::: "memory")
#define CP_WAIT0()  asm volatile("cp.async.wait_group 0;\n" ::: "memory")

__device__ __forceinline__ void ldmx4(unsigned &r0, unsigned &r1, unsigned &r2, unsigned &r3,
                                      uint32_t addr){
    asm volatile("ldmatrix.sync.aligned.m8n8.x4.shared.b16 {%0,%1,%2,%3}, [%4];"
      : "=r"(r0), "=r"(r1), "=r"(r2), "=r"(r3) : "r"(addr));
}

__device__ __forceinline__ void mma16(float d[4], const unsigned a[4], const unsigned b[2]){
    asm volatile(
      "mma.sync.aligned.m16n8k16.row.col.f32.f16.f16.f32 "
      "{%0,%1,%2,%3}, {%4,%5,%6,%7}, {%8,%9}, {%0,%1,%2,%3};\n"
      : "+f"(d[0]), "+f"(d[1]), "+f"(d[2]), "+f"(d[3])
      : "r"(a[0]), "r"(a[1]), "r"(a[2]), "r"(a[3]), "r"(b[0]), "r"(b[1]));
}

__device__ __forceinline__ unsigned pack2(float a, float b){
    __half2 h = __floats2half2_rn(a, b);
    return *reinterpret_cast<unsigned*>(&h);
}

// -------- weight prep: convert all 4 weight matrices to fp16 --------
__global__ void prep_w(const float* __restrict__ wk, const float* __restrict__ wv,
                       const float* __restrict__ wr, const float* __restrict__ wo)
{
    int i = blockIdx.x * blockDim.x + threadIdx.x;
    if (i >= WN) return;
    g_wh[i       ] = __float2half_rn(wk[i]);
    g_wh[i +   WN] = __float2half_rn(wv[i]);
    g_wh[i + 2*WN] = __float2half_rn(wr[i]);
    g_wh[i + 3*WN] = __float2half_rn(wo[i]);
}

// -------- GEMM: C[m,n] = sum_k A[m,k] * W[n,k], fp16 m16n8k16 --------
#define BM 128
#define BN 128
#define BK 32
#define NKI (Cq/BK)     // 24
#define PITCH 40        // halfs per row (80B)
#define TILE_H (BM*PITCH)

template<bool MIXED>
__global__ __launch_bounds__(256, 2) void gemm_fp16(
    const float* __restrict__ x,
    const float* __restrict__ mk, const float* __restrict__ mv, const float* __restrict__ mr,
    float* __restrict__ Cext)
{
    __shared__ __align__(16) __half smA[2][TILE_H];
    __shared__ __align__(16) __half smB[2][TILE_H];

    const __half* W;
    const float* mix = nullptr;
    float* Cout;
    const float* Ap;
    int z = MIXED ? blockIdx.z : 0;
    if (MIXED) {
        W    = g_wh + (size_t)z*WN;
        mix  = (z==0) ? mk : (z==1) ? mv : mr;
        Cout = (z==0) ? g_k : (z==1) ? g_v : g_sr;
        Ap   = x;
    } else {
        W = g_wh + (size_t)3*WN; Cout = Cext; Ap = g_y;
    }

    const int m0 = blockIdx.y * BM;
    const int n0 = blockIdx.x * BN;
    const int tid  = threadIdx.x;
    const int lane = tid & 31;
    const int wid  = tid >> 5;
    const int wm = wid & 3;
    const int wn = wid >> 2;
    const int grp8 = lane >> 2;
    const int c4   = lane & 3;

    const uint32_t uA = (uint32_t)__cvta_generic_to_shared(&smA[0][0]);
    const uint32_t uB = (uint32_t)__cvta_generic_to_shared(&smB[0][0]);

    const int q = lane >> 3, rr = lane & 7;
    const uint32_t aOff = (uint32_t)((wm*32 + ((q&1)<<3) + rr)*80 + (q>>1)*16);
    const uint32_t bOff = (uint32_t)((wn*64 + ((q>>1)<<3) + rr)*80 + (q&1)*16);

    uint4 aU[2];
    auto loadA = [&](int kt){
        #pragma unroll
        for (int p=0;p<2;p++){
            int linear = p*256 + tid;
            int row = linear >> 2, seg = linear & 3;
            int m = m0 + row;
            int kk = kt + seg*8;
            float4 v0, v1;
            if (MIXED) {
                int t  = m & (Tq-1);
                int bb = m >> 10;
                int grp = kk / 192;
                int wq = t & 31, hq = t >> 5;
                int tt; bool valid;
                if      (grp==0) { tt = t-1;  valid = (wq > 0);  }
                else if (grp==1) { tt = t+1;  valid = (wq < 31); }
                else if (grp==2) { tt = t-32; valid = (hq > 0);  }
                else             { tt = t+32; valid = (hq < 31); }
                const float* xb = Ap + (size_t)m*Cq + kk;
                float4 xv0 = *reinterpret_cast<const float4*>(xb);
                float4 xv1 = *reinterpret_cast<const float4*>(xb + 4);
                float4 xs0 = make_float4(0.f,0.f,0.f,0.f);
                float4 xs1 = make_float4(0.f,0.f,0.f,0.f);
                if (valid){
                    const float* sb = Ap + ((size_t)(bb<<10) + tt)*Cq + kk;
                    xs0 = *reinterpret_cast<const float4*>(sb);
                    xs1 = *reinterpret_cast<const float4*>(sb + 4);
                }
                float4 mx0 = *reinterpret_cast<const float4*>(mix + kk);
                float4 mx1 = *reinterpret_cast<const float4*>(mix + kk + 4);
                v0.x = mx0.x*(xv0.x - xs0.x) + xs0.x;
                v0.y = mx0.y*(xv0.y - xs0.y) + xs0.y;
                v0.z = mx0.z*(xv0.z - xs0.z) + xs0.z;
                v0.w = mx0.w*(xv0.w - xs0.w) + xs0.w;
                v1.x = mx1.x*(xv1.x - xs1.x) + xs1.x;
                v1.y = mx1.y*(xv1.y - xs1.y) + xs1.y;
                v1.z = mx1.z*(xv1.z - xs1.z) + xs1.z;
                v1.w = mx1.w*(xv1.w - xs1.w) + xs1.w;
            } else {
                const float* yb = Ap + (size_t)m*Cq + kk;
                v0 = *reinterpret_cast<const float4*>(yb);
                v1 = *reinterpret_cast<const float4*>(yb + 4);
            }
            aU[p].x = pack2(v0.x, v0.y);
            aU[p].y = pack2(v0.z, v0.w);
            aU[p].z = pack2(v1.x, v1.y);
            aU[p].w = pack2(v1.z, v1.w);
        }
    };
    auto storeA = [&](int buf){
        #pragma unroll
        for (int p=0;p<2;p++){
            int linear = p*256 + tid;
            int row = linear >> 2, seg = linear & 3;
            *reinterpret_cast<uint4*>(&smA[buf][row*PITCH + seg*8]) = aU[p];
        }
    };
    auto loadB = [&](int buf, int kt){
        uint32_t base = uB + buf*(TILE_H*2);
        #pragma unroll
        for (int p=0;p<2;p++){
            int linear = p*256 + tid;
            int row = linear >> 2, seg = linear & 3;
            cp_async16(base + (uint32_t)(row*80 + seg*16),
                       W + (size_t)(n0+row)*Cq + kt + seg*8);
        }
    };

    float acc[2][8][4];
    #pragma unroll
    for (int i=0;i<2;i++)
      #pragma unroll
      for (int j=0;j<8;j++)
        #pragma unroll
        for (int qd=0;qd<4;qd++) acc[i][j][qd] = 0.f;

    loadA(0);
    loadB(0, 0); CP_COMMIT();
    storeA(0);
    CP_WAIT0();
    __syncthreads();

    for (int it = 0; it < NKI; it++){
        int cur = it & 1;
        if (it + 1 < NKI){
            loadB(cur^1, (it+1)*BK); CP_COMMIT();
            loadA((it+1)*BK);
        }

        uint32_t aBuf = uA + cur*(TILE_H*2);
        uint32_t bBuf = uB + cur*(TILE_H*2);
        #pragma unroll
        for (int ks=0; ks<2; ks++){
            unsigned afr[2][4];
            #pragma unroll
            for (int i=0;i<2;i++)
                ldmx4(afr[i][0], afr[i][1], afr[i][2], afr[i][3],
                      aBuf + aOff + (uint32_t)(i*1280 + ks*32));
            unsigned bfr[8][2];
            #pragma unroll
            for (int jp=0;jp<4;jp++)
                ldmx4(bfr[2*jp][0], bfr[2*jp][1], bfr[2*jp+1][0], bfr[2*jp+1][1],
                      bBuf + bOff + (uint32_t)(jp*1280 + ks*32));
            #pragma unroll
            for (int i=0;i<2;i++)
                #pragma unroll
                for (int j=0;j<8;j++)
                    mma16(acc[i][j], afr[i], bfr[j]);
        }

        if (it + 1 < NKI){
            storeA(cur^1);
            CP_WAIT0();
        }
        __syncthreads();
    }

    #pragma unroll
    for (int i=0;i<2;i++){
        int r = m0 + wm*32 + i*16 + grp8;
        #pragma unroll
        for (int j=0;j<8;j++){
            int col = n0 + wn*64 + j*8 + 2*c4;
            float v0 = acc[i][j][0], v1 = acc[i][j][1];
            float v2 = acc[i][j][2], v3 = acc[i][j][3];
            if (MIXED && z == 0){   // store exp(k) directly
                v0 = __expf(v0); v1 = __expf(v1);
                v2 = __expf(v2); v3 = __expf(v3);
            }
            if (MIXED && z == 2){
                v0 = 1.f/(1.f+__expf(-v0)); v1 = 1.f/(1.f+__expf(-v1));
                v2 = 1.f/(1.f+__expf(-v2)); v3 = 1.f/(1.f+__expf(-v3));
            }
            *reinterpret_cast<float2*>(Cout + (size_t)r*Cq + col)     = make_float2(v0, v1);
            *reinterpret_cast<float2*>(Cout + (size_t)(r+8)*Cq + col) = make_float2(v2, v3);
        }
    }
}

// ================= chunked bi_wkv scan (g_k holds exp(k)) =================
__device__ __forceinline__ float ew_of(float d){
    return __expf(-__expf(d * (1.0f / (float)Tq)));
}

// Phase A: chunk-local sums, 2 channels/thread. grid (Ss, Bq), block 384.
__global__ __launch_bounds__(384) void wkv_chunk(const float* __restrict__ decay)
{
    int s = blockIdx.x, b = blockIdx.y;
    int pr = threadIdx.x;            // pair index 0..383, channels 2*pr, 2*pr+1
    float2 dc = *reinterpret_cast<const float2*>(decay + 2*pr);
    float ew0 = ew_of(dc.x), ew1 = ew_of(dc.y);

    size_t base = ((size_t)b*Tq + s*Ls)*Cq + 2*pr;

    float fF0=0.f, dF0=0.f, fB0=0.f, dB0=0.f, pw0=1.f;
    float fF1=0.f, dF1=0.f, fB1=0.f, dB1=0.f, pw1=1.f;
    #pragma unroll
    for (int i=0;i<Ls;i++){
        size_t idx = base + (size_t)i*Cq;
        float2 ek = *reinterpret_cast<const float2*>(g_k + idx);
        float2 vv = *reinterpret_cast<const float2*>(g_v + idx);
        fF0 = fmaf(ew0, fF0, ek.x*vv.x);  dF0 = fmaf(ew0, dF0, ek.x);
        fF1 = fmaf(ew1, fF1, ek.y*vv.y);  dF1 = fmaf(ew1, dF1, ek.y);
        fB0 = fmaf(pw0, ek.x*vv.x, fB0);  dB0 = fmaf(pw0, ek.x, dB0);
        fB1 = fmaf(pw1, ek.y*vv.y, fB1);  dB1 = fmaf(pw1, ek.y, dB1);
        pw0 *= ew0; pw1 *= ew1;
    }
    size_t ci = ((size_t)b*Ss + s)*(Cq/2) + pr;
    g_cFP[ci] = make_float4(fF0, dF0, fF1, dF1);
    g_cBP[ci] = make_float4(fB0, dB0, fB1, dB1);
}

// Phase B: carry scan per channel-pair, one float4 load/step. gridDim.y = dir.
__global__ __launch_bounds__(256) void wkv_carry(const float* __restrict__ decay)
{
    int p = blockIdx.x * blockDim.x + threadIdx.x;
    if (p >= NBC/2) return;
    int b = p / (Cq/2), pr = p % (Cq/2);
    float2 dc = *reinterpret_cast<const float2*>(decay + 2*pr);
    float ew0 = ew_of(dc.x), ew1 = ew_of(dc.y);
    float a0 = ew0*ew0; a0*=a0; a0*=a0; a0*=a0;   // ew0^16
    float a1 = ew1*ew1; a1*=a1; a1*=a1; a1*=a1;   // ew1^16
    size_t base = (size_t)b*Ss*(Cq/2) + pr;

    if (blockIdx.y == 0){
        float4 st = make_float4(0,0,0,0);
        #pragma unroll 8
        for (int s=0;s<Ss;s++){
            size_t ci = base + (size_t)s*(Cq/2);
            float4 cf = g_cFP[ci];
            g_FiP[ci] = st;
            st.x = fmaf(a0, st.x, cf.x);  st.y = fmaf(a0, st.y, cf.y);
            st.z = fmaf(a1, st.z, cf.z);  st.w = fmaf(a1, st.w, cf.w);
        }
    } else {
        float4 st = make_float4(0,0,0,0);
        #pragma unroll 8
        for (int s=Ss-1;s>=0;s--){
            size_t ci = base + (size_t)s*(Cq/2);
            float4 cb = g_cBP[ci];
            g_BiP[ci] = st;
            st.x = fmaf(a0, st.x, cb.x);  st.y = fmaf(a0, st.y, cb.y);
            st.z = fmaf(a1, st.z, cb.z);  st.w = fmaf(a1, st.w, cb.w);
        }
    }
}

// Phase C: apply carries, 2 channels/thread. grid (Ss, Bq*3), block 128.
__global__ __launch_bounds__(128) void wkv_apply(const float* __restrict__ decay,
                                                 const float* __restrict__ first)
{
    int s = blockIdx.x;
    int b = blockIdx.y / 3;
    int pr = (blockIdx.y % 3)*128 + threadIdx.x;   // pair index 0..383
    float2 dc = *reinterpret_cast<const float2*>(decay + 2*pr);
    float2 fu = *reinterpret_cast<const float2*>(first + 2*pr);
    float ew0 = ew_of(dc.x), ew1 = ew_of(dc.y);
    float eu0 = __expf(fu.x * (1.0f/(float)Tq));
    float eu1 = __expf(fu.y * (1.0f/(float)Tq));

    size_t base = ((size_t)b*Tq + s*Ls)*Cq + 2*pr;
    size_t ci   = ((size_t)b*Ss + s)*(Cq/2) + pr;

    // backward micro-scan (exclusive per element)
    float bn0A[Ls], bd0A[Ls], bn1A[Ls], bd1A[Ls];
    float4 bi = g_BiP[ci];
    float bn0 = bi.x, bd0 = bi.y, bn1 = bi.z, bd1 = bi.w;
    #pragma unroll
    for (int i=Ls-1;i>=0;i--){
        size_t idx = base + (size_t)i*Cq;
        float2 ek = *reinterpret_cast<const float2*>(g_k + idx);
        float2 vv = *reinterpret_cast<const float2*>(g_v + idx);
        bn0A[i] = bn0; bd0A[i] = bd0;
        bn1A[i] = bn1; bd1A[i] = bd1;
        bn0 = fmaf(ew0, bn0, ek.x*vv.x);  bd0 = fmaf(ew0, bd0, ek.x);
        bn1 = fmaf(ew1, bn1, ek.y*vv.y);  bd1 = fmaf(ew1, bd1, ek.y);
    }

    // forward micro-scan + combine + sr multiply
    float4 fi = g_FiP[ci];
    float fn0 = fi.x, fd0 = fi.y, fn1 = fi.z, fd1 = fi.w;
    #pragma unroll
    for (int i=0;i<Ls;i++){
        size_t idx = base + (size_t)i*Cq;
        float2 ek = *reinterpret_cast<const float2*>(g_k + idx);
        float2 vv = *reinterpret_cast<const float2*>(g_v + idx);
        float2 sr = *reinterpret_cast<const float2*>(g_sr + idx);
        float e0 = eu0 * ek.x, e1 = eu1 * ek.y;
        float o0 = (fn0 + bn0A[i] + e0*vv.x) / (fd0 + bd0A[i] + e0);
        float o1 = (fn1 + bn1A[i] + e1*vv.y) / (fd1 + bd1A[i] + e1);
        *reinterpret_cast<float2*>(g_y + idx) = make_float2(sr.x*o0, sr.y*o1);
        fn0 = fmaf(ew0, fn0, ek.x*vv.x);  fd0 = fmaf(ew0, fd0, ek.x);
        fn1 = fmaf(ew1, fn1, ek.y*vv.y);  fd1 = fmaf(ew1, fd1, ek.y);
    }
}

extern "C" void kernel_launch(void* const* d_in, const int* in_sizes, int n_in,
                              void* d_out, int out_size)
{
    const float* x       = (const float*)d_in[0];
    const float* key_w   = (const float*)d_in[1];
    const float* value_w = (const float*)d_in[2];
    const float* recep_w = (const float*)d_in[3];
    const float* out_w   = (const float*)d_in[4];
    const float* decay   = (const float*)d_in[5];
    const float* first   = (const float*)d_in[6];
    const float* mk      = (const float*)d_in[7];
    const float* mv      = (const float*)d_in[8];
    const float* mr      = (const float*)d_in[9];
    float* out = (float*)d_out;

    // 0) convert weights to fp16
    prep_w<<<(WN+255)/256, 256>>>(key_w, value_w, recep_w, out_w);

    // 1) exp(k), v, sr
    dim3 grid1(Cq/BN, Mq/BM, 3);
    gemm_fp16<true><<<grid1, 256>>>(x, mk, mv, mr, nullptr);

    // 2) chunked bidirectional scan (vectorized)
    wkv_chunk<<<dim3(Ss, Bq), 384>>>(decay);
    wkv_carry<<<dim3((NBC/2 + 255)/256, 2), 256>>>(decay);
    wkv_apply<<<dim3(Ss, Bq*3), 128>>>(decay, first);

    // 3) out = (sr * rwkv) @ output_w^T
    dim3 grid2(Cq/BN, Mq/BM, 1);
    gemm_fp16<false><<<grid2, 256>>>(nullptr, nullptr, nullptr, nullptr, out);
}

// round 15
// speedup vs baseline: 1.8635x; 1.0959x over previous
#include <cuda_runtime.h>
#include <cuda_fp16.h>
#include <cstdint>

// Problem constants
#define Bq 16
#define Tq 1024
#define Cq 768
#define Mq (Bq*Tq)          // 16384
#define NBC (Bq*Cq)         // 12288
#define Ls 16               // chunk length
#define Ss 64               // num chunks (Ls*Ss == Tq)
#define WN (Cq*Cq)          // 589824 weight elements
#define CPAIR (Bq*Ss*(Cq/2))   // channel-pair carry count

// -------- device scratch (static, no allocations) --------
__device__ __half g_k [12582912];  // exp(k), fp16
__device__ __half g_v [12582912];  // v, fp16
__device__ __half g_sr[12582912];  // sigmoid(r), fp16
__device__ __half g_y [12582912];  // sr*wkv, fp16 (A of final GEMM)
__device__ __half g_wh[4*WN];      // fp16 weights: k,v,r,o
// carries packed per channel-pair: (num0, den0, num1, den1), fp32
__device__ float4 g_cFP[CPAIR];
__device__ float4 g_cBP[CPAIR];
__device__ float4 g_FiP[CPAIR];
__device__ float4 g_BiP[CPAIR];

// -------- helpers --------
__device__ __forceinline__ void cp_async16(uint32_t smem_dst, const void* gmem_src){
    asm volatile("cp.async.ca.shared.global [%0], [%1], 16;\n" :: "r"(smem_dst), "l"(gmem_src));
}
#define CP_COMMIT() asm volatile("cp.async.commit_group;\n" ::: "memory")
#define CP_WAIT0()  asm volatile("cp.async.wait_group 0;\n" ::: "memory")

__device__ __forceinline__ void ldmx4(unsigned &r0, unsigned &r1, unsigned &r2, unsigned &r3,
                                      uint32_t addr){
    asm volatile("ldmatrix.sync.aligned.m8n8.x4.shared.b16 {%0,%1,%2,%3}, [%4];"
      : "=r"(r0), "=r"(r1), "=r"(r2), "=r"(r3) : "r"(addr));
}

__device__ __forceinline__ void mma16(float d[4], const unsigned a[4], const unsigned b[2]){
    asm volatile(
      "mma.sync.aligned.m16n8k16.row.col.f32.f16.f16.f32 "
      "{%0,%1,%2,%3}, {%4,%5,%6,%7}, {%8,%9}, {%0,%1,%2,%3};\n"
      : "+f"(d[0]), "+f"(d[1]), "+f"(d[2]), "+f"(d[3])
      : "r"(a[0]), "r"(a[1]), "r"(a[2]), "r"(a[3]), "r"(b[0]), "r"(b[1]));
}

__device__ __forceinline__ unsigned pack2(float a, float b){
    __half2 h = __floats2half2_rn(a, b);
    return *reinterpret_cast<unsigned*>(&h);
}

// -------- weight prep: convert all 4 weight matrices to fp16 --------
__global__ void prep_w(const float* __restrict__ wk, const float* __restrict__ wv,
                       const float* __restrict__ wr, const float* __restrict__ wo)
{
    int i = blockIdx.x * blockDim.x + threadIdx.x;
    if (i >= WN) return;
    g_wh[i       ] = __float2half_rn(wk[i]);
    g_wh[i +   WN] = __float2half_rn(wv[i]);
    g_wh[i + 2*WN] = __float2half_rn(wr[i]);
    g_wh[i + 3*WN] = __float2half_rn(wo[i]);
}

// -------- GEMM: C[m,n] = sum_k A[m,k] * W[n,k], fp16 m16n8k16 --------
#define BM 128
#define BN 128
#define BK 32
#define NKI (Cq/BK)     // 24
#define PITCH 40        // halfs per row (80B)
#define TILE_H (BM*PITCH)

template<bool MIXED>
__global__ __launch_bounds__(256, 2) void gemm_fp16(
    const float* __restrict__ x,
    const float* __restrict__ mk, const float* __restrict__ mv, const float* __restrict__ mr,
    float* __restrict__ Cext)
{
    __shared__ __align__(16) __half smA[2][TILE_H];
    __shared__ __align__(16) __half smB[2][TILE_H];

    const __half* W;
    const float* mix = nullptr;
    __half* CoutH = nullptr;
    int z = MIXED ? blockIdx.z : 0;
    if (MIXED) {
        W     = g_wh + (size_t)z*WN;
        mix   = (z==0) ? mk : (z==1) ? mv : mr;
        CoutH = (z==0) ? g_k : (z==1) ? g_v : g_sr;
    } else {
        W = g_wh + (size_t)3*WN;
    }

    const int m0 = blockIdx.y * BM;
    const int n0 = blockIdx.x * BN;
    const int tid  = threadIdx.x;
    const int lane = tid & 31;
    const int wid  = tid >> 5;
    const int wm = wid & 3;
    const int wn = wid >> 2;
    const int grp8 = lane >> 2;
    const int c4   = lane & 3;

    const uint32_t uA = (uint32_t)__cvta_generic_to_shared(&smA[0][0]);
    const uint32_t uB = (uint32_t)__cvta_generic_to_shared(&smB[0][0]);

    const int q = lane >> 3, rr = lane & 7;
    const uint32_t aOff = (uint32_t)((wm*32 + ((q&1)<<3) + rr)*80 + (q>>1)*16);
    const uint32_t bOff = (uint32_t)((wn*64 + ((q>>1)<<3) + rr)*80 + (q&1)*16);

    uint4 aU[2];
    auto loadA = [&](int kt){
        #pragma unroll
        for (int p=0;p<2;p++){
            int linear = p*256 + tid;
            int row = linear >> 2, seg = linear & 3;
            int m = m0 + row;
            int kk = kt + seg*8;
            if (MIXED) {
                int t  = m & (Tq-1);
                int bb = m >> 10;
                int grp = kk / 192;
                int wq = t & 31, hq = t >> 5;
                int tt; bool valid;
                if      (grp==0) { tt = t-1;  valid = (wq > 0);  }
                else if (grp==1) { tt = t+1;  valid = (wq < 31); }
                else if (grp==2) { tt = t-32; valid = (hq > 0);  }
                else             { tt = t+32; valid = (hq < 31); }
                const float* xb = x + (size_t)m*Cq + kk;
                float4 xv0 = *reinterpret_cast<const float4*>(xb);
                float4 xv1 = *reinterpret_cast<const float4*>(xb + 4);
                float4 xs0 = make_float4(0.f,0.f,0.f,0.f);
                float4 xs1 = make_float4(0.f,0.f,0.f,0.f);
                if (valid){
                    const float* sb = x + ((size_t)(bb<<10) + tt)*Cq + kk;
                    xs0 = *reinterpret_cast<const float4*>(sb);
                    xs1 = *reinterpret_cast<const float4*>(sb + 4);
                }
                float4 mx0 = *reinterpret_cast<const float4*>(mix + kk);
                float4 mx1 = *reinterpret_cast<const float4*>(mix + kk + 4);
                float4 v0, v1;
                v0.x = mx0.x*(xv0.x - xs0.x) + xs0.x;
                v0.y = mx0.y*(xv0.y - xs0.y) + xs0.y;
                v0.z = mx0.z*(xv0.z - xs0.z) + xs0.z;
                v0.w = mx0.w*(xv0.w - xs0.w) + xs0.w;
                v1.x = mx1.x*(xv1.x - xs1.x) + xs1.x;
                v1.y = mx1.y*(xv1.y - xs1.y) + xs1.y;
                v1.z = mx1.z*(xv1.z - xs1.z) + xs1.z;
                v1.w = mx1.w*(xv1.w - xs1.w) + xs1.w;
                aU[p].x = pack2(v0.x, v0.y);
                aU[p].y = pack2(v0.z, v0.w);
                aU[p].z = pack2(v1.x, v1.y);
                aU[p].w = pack2(v1.z, v1.w);
            } else {
                // y is already fp16: one 16B load of 8 halfs
                aU[p] = *reinterpret_cast<const uint4*>(g_y + (size_t)m*Cq + kk);
            }
        }
    };
    auto storeA = [&](int buf){
        #pragma unroll
        for (int p=0;p<2;p++){
            int linear = p*256 + tid;
            int row = linear >> 2, seg = linear & 3;
            *reinterpret_cast<uint4*>(&smA[buf][row*PITCH + seg*8]) = aU[p];
        }
    };
    auto loadB = [&](int buf, int kt){
        uint32_t base = uB + buf*(TILE_H*2);
        #pragma unroll
        for (int p=0;p<2;p++){
            int linear = p*256 + tid;
            int row = linear >> 2, seg = linear & 3;
            cp_async16(base + (uint32_t)(row*80 + seg*16),
                       W + (size_t)(n0+row)*Cq + kt + seg*8);
        }
    };

    float acc[2][8][4];
    #pragma unroll
    for (int i=0;i<2;i++)
      #pragma unroll
      for (int j=0;j<8;j++)
        #pragma unroll
        for (int qd=0;qd<4;qd++) acc[i][j][qd] = 0.f;

    loadA(0);
    loadB(0, 0); CP_COMMIT();
    storeA(0);
    CP_WAIT0();
    __syncthreads();

    for (int it = 0; it < NKI; it++){
        int cur = it & 1;
        if (it + 1 < NKI){
            loadB(cur^1, (it+1)*BK); CP_COMMIT();
            loadA((it+1)*BK);
        }

        uint32_t aBuf = uA + cur*(TILE_H*2);
        uint32_t bBuf = uB + cur*(TILE_H*2);
        #pragma unroll
        for (int ks=0; ks<2; ks++){
            unsigned afr[2][4];
            #pragma unroll
            for (int i=0;i<2;i++)
                ldmx4(afr[i][0], afr[i][1], afr[i][2], afr[i][3],
                      aBuf + aOff + (uint32_t)(i*1280 + ks*32));
            unsigned bfr[8][2];
            #pragma unroll
            for (int jp=0;jp<4;jp++)
                ldmx4(bfr[2*jp][0], bfr[2*jp][1], bfr[2*jp+1][0], bfr[2*jp+1][1],
                      bBuf + bOff + (uint32_t)(jp*1280 + ks*32));
            #pragma unroll
            for (int i=0;i<2;i++)
                #pragma unroll
                for (int j=0;j<8;j++)
                    mma16(acc[i][j], afr[i], bfr[j]);
        }

        if (it + 1 < NKI){
            storeA(cur^1);
            CP_WAIT0();
        }
        __syncthreads();
    }

    // ---- epilogue ----
    #pragma unroll
    for (int i=0;i<2;i++){
        int r = m0 + wm*32 + i*16 + grp8;
        #pragma unroll
        for (int j=0;j<8;j++){
            int col = n0 + wn*64 + j*8 + 2*c4;
            float v0 = acc[i][j][0], v1 = acc[i][j][1];
            float v2 = acc[i][j][2], v3 = acc[i][j][3];
            if (MIXED){
                if (z == 0){   // store exp(k)
                    v0 = __expf(v0); v1 = __expf(v1);
                    v2 = __expf(v2); v3 = __expf(v3);
                } else if (z == 2){
                    v0 = 1.f/(1.f+__expf(-v0)); v1 = 1.f/(1.f+__expf(-v1));
                    v2 = 1.f/(1.f+__expf(-v2)); v3 = 1.f/(1.f+__expf(-v3));
                }
                *reinterpret_cast<unsigned*>(CoutH + (size_t)r*Cq + col)     = pack2(v0, v1);
                *reinterpret_cast<unsigned*>(CoutH + (size_t)(r+8)*Cq + col) = pack2(v2, v3);
            } else {
                *reinterpret_cast<float2*>(Cext + (size_t)r*Cq + col)     = make_float2(v0, v1);
                *reinterpret_cast<float2*>(Cext + (size_t)(r+8)*Cq + col) = make_float2(v2, v3);
            }
        }
    }
}

// ================= chunked bi_wkv scan (g_k holds exp(k), fp16) =================
__device__ __forceinline__ float ew_of(float d){
    return __expf(-__expf(d * (1.0f / (float)Tq)));
}

// Phase A: chunk-local sums, 2 channels/thread. grid (Ss, Bq), block 384.
__global__ __launch_bounds__(384) void wkv_chunk(const float* __restrict__ decay)
{
    int s = blockIdx.x, b = blockIdx.y;
    int pr = threadIdx.x;            // pair index 0..383
    float2 dc = *reinterpret_cast<const float2*>(decay + 2*pr);
    float ew0 = ew_of(dc.x), ew1 = ew_of(dc.y);

    size_t base = ((size_t)b*Tq + s*Ls)*Cq + 2*pr;

    float fF0=0.f, dF0=0.f, fB0=0.f, dB0=0.f, pw0=1.f;
    float fF1=0.f, dF1=0.f, fB1=0.f, dB1=0.f, pw1=1.f;
    #pragma unroll
    for (int i=0;i<Ls;i++){
        size_t idx = base + (size_t)i*Cq;
        float2 ek = __half22float2(*reinterpret_cast<const __half2*>(g_k + idx));
        float2 vv = __half22float2(*reinterpret_cast<const __half2*>(g_v + idx));
        fF0 = fmaf(ew0, fF0, ek.x*vv.x);  dF0 = fmaf(ew0, dF0, ek.x);
        fF1 = fmaf(ew1, fF1, ek.y*vv.y);  dF1 = fmaf(ew1, dF1, ek.y);
        fB0 = fmaf(pw0, ek.x*vv.x, fB0);  dB0 = fmaf(pw0, ek.x, dB0);
        fB1 = fmaf(pw1, ek.y*vv.y, fB1);  dB1 = fmaf(pw1, ek.y, dB1);
        pw0 *= ew0; pw1 *= ew1;
    }
    size_t ci = ((size_t)b*Ss + s)*(Cq/2) + pr;
    g_cFP[ci] = make_float4(fF0, dF0, fF1, dF1);
    g_cBP[ci] = make_float4(fB0, dB0, fB1, dB1);
}

// Phase B: carry scan per channel-pair. gridDim.y = direction.
__global__ __launch_bounds__(256) void wkv_carry(const float* __restrict__ decay)
{
    int p = blockIdx.x * blockDim.x + threadIdx.x;
    if (p >= NBC/2) return;
    int b = p / (Cq/2), pr = p % (Cq/2);
    float2 dc = *reinterpret_cast<const float2*>(decay + 2*pr);
    float ew0 = ew_of(dc.x), ew1 = ew_of(dc.y);
    float a0 = ew0*ew0; a0*=a0; a0*=a0; a0*=a0;   // ew0^16
    float a1 = ew1*ew1; a1*=a1; a1*=a1; a1*=a1;   // ew1^16
    size_t base = (size_t)b*Ss*(Cq/2) + pr;

    if (blockIdx.y == 0){
        float4 st = make_float4(0,0,0,0);
        #pragma unroll 8
        for (int s=0;s<Ss;s++){
            size_t ci = base + (size_t)s*(Cq/2);
            float4 cf = g_cFP[ci];
            g_FiP[ci] = st;
            st.x = fmaf(a0, st.x, cf.x);  st.y = fmaf(a0, st.y, cf.y);
            st.z = fmaf(a1, st.z, cf.z);  st.w = fmaf(a1, st.w, cf.w);
        }
    } else {
        float4 st = make_float4(0,0,0,0);
        #pragma unroll 8
        for (int s=Ss-1;s>=0;s--){
            size_t ci = base + (size_t)s*(Cq/2);
            float4 cb = g_cBP[ci];
            g_BiP[ci] = st;
            st.x = fmaf(a0, st.x, cb.x);  st.y = fmaf(a0, st.y, cb.y);
            st.z = fmaf(a1, st.z, cb.z);  st.w = fmaf(a1, st.w, cb.w);
        }
    }
}

// Phase C: apply carries, 2 channels/thread. grid (Ss, Bq*3), block 128.
__global__ __launch_bounds__(128) void wkv_apply(const float* __restrict__ decay,
                                                 const float* __restrict__ first)
{
    int s = blockIdx.x;
    int b = blockIdx.y / 3;
    int pr = (blockIdx.y % 3)*128 + threadIdx.x;   // pair index 0..383
    float2 dc = *reinterpret_cast<const float2*>(decay + 2*pr);
    float2 fu = *reinterpret_cast<const float2*>(first + 2*pr);
    float ew0 = ew_of(dc.x), ew1 = ew_of(dc.y);
    float eu0 = __expf(fu.x * (1.0f/(float)Tq));
    float eu1 = __expf(fu.y * (1.0f/(float)Tq));

    size_t base = ((size_t)b*Tq + s*Ls)*Cq + 2*pr;
    size_t ci   = ((size_t)b*Ss + s)*(Cq/2) + pr;

    // backward micro-scan (exclusive per element)
    float bn0A[Ls], bd0A[Ls], bn1A[Ls], bd1A[Ls];
    float4 bi = g_BiP[ci];
    float bn0 = bi.x, bd0 = bi.y, bn1 = bi.z, bd1 = bi.w;
    #pragma unroll
    for (int i=Ls-1;i>=0;i--){
        size_t idx = base + (size_t)i*Cq;
        float2 ek = __half22float2(*reinterpret_cast<const __half2*>(g_k + idx));
        float2 vv = __half22float2(*reinterpret_cast<const __half2*>(g_v + idx));
        bn0A[i] = bn0; bd0A[i] = bd0;
        bn1A[i] = bn1; bd1A[i] = bd1;
        bn0 = fmaf(ew0, bn0, ek.x*vv.x);  bd0 = fmaf(ew0, bd0, ek.x);
        bn1 = fmaf(ew1, bn1, ek.y*vv.y);  bd1 = fmaf(ew1, bd1, ek.y);
    }

    // forward micro-scan + combine + sr multiply
    float4 fi = g_FiP[ci];
    float fn0 = fi.x, fd0 = fi.y, fn1 = fi.z, fd1 = fi.w;
    #pragma unroll
    for (int i=0;i<Ls;i++){
        size_t idx = base + (size_t)i*Cq;
        float2 ek = __half22float2(*reinterpret_cast<const __half2*>(g_k + idx));
        float2 vv = __half22float2(*reinterpret_cast<const __half2*>(g_v + idx));
        float2 sr = __half22float2(*reinterpret_cast<const __half2*>(g_sr + idx));
        float e0 = eu0 * ek.x, e1 = eu1 * ek.y;
        float o0 = (fn0 + bn0A[i] + e0*vv.x) / (fd0 + bd0A[i] + e0);
        float o1 = (fn1 + bn1A[i] + e1*vv.y) / (fd1 + bd1A[i] + e1);
        *reinterpret_cast<__half2*>(g_y + idx) = __floats2half2_rn(sr.x*o0, sr.y*o1);
        fn0 = fmaf(ew0, fn0, ek.x*vv.x);  fd0 = fmaf(ew0, fd0, ek.x);
        fn1 = fmaf(ew1, fn1, ek.y*vv.y);  fd1 = fmaf(ew1, fd1, ek.y);
    }
}

extern "C" void kernel_launch(void* const* d_in, const int* in_sizes, int n_in,
                              void* d_out, int out_size)
{
    const float* x       = (const float*)d_in[0];
    const float* key_w   = (const float*)d_in[1];
    const float* value_w = (const float*)d_in[2];
    const float* recep_w = (const float*)d_in[3];
    const float* out_w   = (const float*)d_in[4];
    const float* decay   = (const float*)d_in[5];
    const float* first   = (const float*)d_in[6];
    const float* mk      = (const float*)d_in[7];
    const float* mv      = (const float*)d_in[8];
    const float* mr      = (const float*)d_in[9];
    float* out = (float*)d_out;

    // 0) convert weights to fp16
    prep_w<<<(WN+255)/256, 256>>>(key_w, value_w, recep_w, out_w);

    // 1) exp(k), v, sr  (fp16 outputs)
    dim3 grid1(Cq/BN, Mq/BM, 3);
    gemm_fp16<true><<<grid1, 256>>>(x, mk, mv, mr, nullptr);

    // 2) chunked bidirectional scan
    wkv_chunk<<<dim3(Ss, Bq), 384>>>(decay);
    wkv_carry<<<dim3((NBC/2 + 255)/256, 2), 256>>>(decay);
    wkv_apply<<<dim3(Ss, Bq*3), 128>>>(decay, first);

    // 3) out = y @ output_w^T  (y already fp16)
    dim3 grid2(Cq/BN, Mq/BM, 1);
    gemm_fp16<false><<<grid2, 256>>>(nullptr, nullptr, nullptr, nullptr, out);
}

// round 16
// speedup vs baseline: 2.1808x; 1.1703x over previous
#include <cuda_runtime.h>
#include <cuda_fp16.h>
#include <cstdint>

// Problem constants
#define Bq 16
#define Tq 1024
#define Cq 768
#define Mq (Bq*Tq)          // 16384
#define NBC (Bq*Cq)         // 12288
#define Ls 16               // chunk length
#define Ss 64               // num chunks (Ls*Ss == Tq)
#define WN (Cq*Cq)          // 589824 weight elements
#define ASZ 12582912        // Mq*Cq
#define CPAIR (Bq*Ss*(Cq/2))   // channel-pair carry count

// -------- device scratch (static, no allocations) --------
__device__ __half g_xm[3*ASZ];     // premixed A matrices: xk, xv, xr (fp16)
__device__ __half g_k [ASZ];       // exp(k), fp16
__device__ __half g_v [ASZ];       // v, fp16
__device__ __half g_sr[ASZ];       // sigmoid(r), fp16
__device__ __half g_y [ASZ];       // sr*wkv, fp16 (A of final GEMM)
__device__ __half g_wh[4*WN];      // fp16 weights: k,v,r,o
// carries packed per channel-pair: (num0, den0, num1, den1), fp32
__device__ float4 g_cFP[CPAIR];
__device__ float4 g_cBP[CPAIR];
__device__ float4 g_FiP[CPAIR];
__device__ float4 g_BiP[CPAIR];

// -------- helpers --------
__device__ __forceinline__ void cp_async16(uint32_t smem_dst, const void* gmem_src){
    asm volatile("cp.async.ca.shared.global [%0], [%1], 16;\n" :: "r"(smem_dst), "l"(gmem_src));
}
#define CP_COMMIT() asm volatile("cp.async.commit_group;\n" ::: "memory")
#define CP_WAIT0()  asm volatile("cp.async.wait_group 0;\n" ::: "memory")

__device__ __forceinline__ void ldmx4(unsigned &r0, unsigned &r1, unsigned &r2, unsigned &r3,
                                      uint32_t addr){
    asm volatile("ldmatrix.sync.aligned.m8n8.x4.shared.b16 {%0,%1,%2,%3}, [%4];"
      : "=r"(r0), "=r"(r1), "=r"(r2), "=r"(r3) : "r"(addr));
}

__device__ __forceinline__ void mma16(float d[4], const unsigned a[4], const unsigned b[2]){
    asm volatile(
      "mma.sync.aligned.m16n8k16.row.col.f32.f16.f16.f32 "
      "{%0,%1,%2,%3}, {%4,%5,%6,%7}, {%8,%9}, {%0,%1,%2,%3};\n"
      : "+f"(d[0]), "+f"(d[1]), "+f"(d[2]), "+f"(d[3])
      : "r"(a[0]), "r"(a[1]), "r"(a[2]), "r"(a[3]), "r"(b[0]), "r"(b[1]));
}

__device__ __forceinline__ unsigned pack2(float a, float b){
    __half2 h = __floats2half2_rn(a, b);
    return *reinterpret_cast<unsigned*>(&h);
}

// -------- weight prep: convert all 4 weight matrices to fp16 --------
__global__ void prep_w(const float* __restrict__ wk, const float* __restrict__ wv,
                       const float* __restrict__ wr, const float* __restrict__ wo)
{
    int i = blockIdx.x * blockDim.x + threadIdx.x;
    if (i >= WN) return;
    g_wh[i       ] = __float2half_rn(wk[i]);
    g_wh[i +   WN] = __float2half_rn(wv[i]);
    g_wh[i + 2*WN] = __float2half_rn(wr[i]);
    g_wh[i + 3*WN] = __float2half_rn(wo[i]);
}

// -------- A prep: q_shift + token mix for all 3 variants, fp16 output --------
// One thread = 4 channels of one token. Math identical (fp32 mix, rn pack).
__global__ __launch_bounds__(256) void prep_a(
    const float* __restrict__ x,
    const float* __restrict__ mk, const float* __restrict__ mv, const float* __restrict__ mr)
{
    int i = blockIdx.x * blockDim.x + threadIdx.x;   // group of 4 channels
    int m  = i / (Cq/4);
    int kk = (i % (Cq/4)) * 4;

    int t  = m & (Tq-1);
    int bb = m >> 10;
    int grp = kk / 192;
    int wq = t & 31, hq = t >> 5;
    int tt; bool valid;
    if      (grp==0) { tt = t-1;  valid = (wq > 0);  }
    else if (grp==1) { tt = t+1;  valid = (wq < 31); }
    else if (grp==2) { tt = t-32; valid = (hq > 0);  }
    else             { tt = t+32; valid = (hq < 31); }

    float4 xv = *reinterpret_cast<const float4*>(x + (size_t)m*Cq + kk);
    float4 xs = make_float4(0.f,0.f,0.f,0.f);
    if (valid)
        xs = *reinterpret_cast<const float4*>(x + ((size_t)(bb<<10) + tt)*Cq + kk);

    size_t off = (size_t)m*Cq + kk;
    const float* mixes[3] = {mk, mv, mr};
    #pragma unroll
    for (int z=0; z<3; z++){
        float4 mx = *reinterpret_cast<const float4*>(mixes[z] + kk);
        float a0 = mx.x*(xv.x - xs.x) + xs.x;
        float a1 = mx.y*(xv.y - xs.y) + xs.y;
        float a2 = mx.z*(xv.z - xs.z) + xs.z;
        float a3 = mx.w*(xv.w - xs.w) + xs.w;
        *reinterpret_cast<uint2*>(g_xm + (size_t)z*ASZ + off) =
            make_uint2(pack2(a0, a1), pack2(a2, a3));
    }
}

// -------- GEMM: C[m,n] = sum_k A[m,k] * W[n,k], fp16 m16n8k16, pure cp.async --------
#define BM 128
#define BN 128
#define BK 32
#define NKI (Cq/BK)     // 24
#define PITCH 40        // halfs per row (80B)
#define TILE_H (BM*PITCH)

template<bool MIXED>
__global__ __launch_bounds__(256, 2) void gemm_fp16(float* __restrict__ Cext)
{
    __shared__ __align__(16) __half smA[2][TILE_H];
    __shared__ __align__(16) __half smB[2][TILE_H];

    int z = MIXED ? blockIdx.z : 0;
    const __half* W    = g_wh + (size_t)(MIXED ? z : 3)*WN;
    const __half* Asrc = MIXED ? (g_xm + (size_t)z*ASZ) : g_y;
    __half* CoutH = nullptr;
    if (MIXED) CoutH = (z==0) ? g_k : (z==1) ? g_v : g_sr;

    const int m0 = blockIdx.y * BM;
    const int n0 = blockIdx.x * BN;
    const int tid  = threadIdx.x;
    const int lane = tid & 31;
    const int wid  = tid >> 5;
    const int wm = wid & 3;
    const int wn = wid >> 2;
    const int grp8 = lane >> 2;
    const int c4   = lane & 3;

    const uint32_t uA = (uint32_t)__cvta_generic_to_shared(&smA[0][0]);
    const uint32_t uB = (uint32_t)__cvta_generic_to_shared(&smB[0][0]);

    const int q = lane >> 3, rr = lane & 7;
    const uint32_t aOff = (uint32_t)((wm*32 + ((q&1)<<3) + rr)*80 + (q>>1)*16);
    const uint32_t bOff = (uint32_t)((wn*64 + ((q>>1)<<3) + rr)*80 + (q&1)*16);

    auto loadA = [&](int buf, int kt){
        uint32_t base = uA + buf*(TILE_H*2);
        #pragma unroll
        for (int p=0;p<2;p++){
            int linear = p*256 + tid;
            int row = linear >> 2, seg = linear & 3;
            cp_async16(base + (uint32_t)(row*80 + seg*16),
                       Asrc + (size_t)(m0+row)*Cq + kt + seg*8);
        }
    };
    auto loadB = [&](int buf, int kt){
        uint32_t base = uB + buf*(TILE_H*2);
        #pragma unroll
        for (int p=0;p<2;p++){
            int linear = p*256 + tid;
            int row = linear >> 2, seg = linear & 3;
            cp_async16(base + (uint32_t)(row*80 + seg*16),
                       W + (size_t)(n0+row)*Cq + kt + seg*8);
        }
    };

    float acc[2][8][4];
    #pragma unroll
    for (int i=0;i<2;i++)
      #pragma unroll
      for (int j=0;j<8;j++)
        #pragma unroll
        for (int qd=0;qd<4;qd++) acc[i][j][qd] = 0.f;

    // prologue
    loadA(0, 0); loadB(0, 0); CP_COMMIT();
    CP_WAIT0();
    __syncthreads();

    for (int it = 0; it < NKI; it++){
        int cur = it & 1;
        if (it + 1 < NKI){
            loadA(cur^1, (it+1)*BK);
            loadB(cur^1, (it+1)*BK);
            CP_COMMIT();
        }

        uint32_t aBuf = uA + cur*(TILE_H*2);
        uint32_t bBuf = uB + cur*(TILE_H*2);
        #pragma unroll
        for (int ks=0; ks<2; ks++){
            unsigned afr[2][4];
            #pragma unroll
            for (int i=0;i<2;i++)
                ldmx4(afr[i][0], afr[i][1], afr[i][2], afr[i][3],
                      aBuf + aOff + (uint32_t)(i*1280 + ks*32));
            unsigned bfr[8][2];
            #pragma unroll
            for (int jp=0;jp<4;jp++)
                ldmx4(bfr[2*jp][0], bfr[2*jp][1], bfr[2*jp+1][0], bfr[2*jp+1][1],
                      bBuf + bOff + (uint32_t)(jp*1280 + ks*32));
            #pragma unroll
            for (int i=0;i<2;i++)
                #pragma unroll
                for (int j=0;j<8;j++)
                    mma16(acc[i][j], afr[i], bfr[j]);
        }

        if (it + 1 < NKI) CP_WAIT0();
        __syncthreads();
    }

    // ---- epilogue ----
    #pragma unroll
    for (int i=0;i<2;i++){
        int r = m0 + wm*32 + i*16 + grp8;
        #pragma unroll
        for (int j=0;j<8;j++){
            int col = n0 + wn*64 + j*8 + 2*c4;
            float v0 = acc[i][j][0], v1 = acc[i][j][1];
            float v2 = acc[i][j][2], v3 = acc[i][j][3];
            if (MIXED){
                if (z == 0){   // store exp(k)
                    v0 = __expf(v0); v1 = __expf(v1);
                    v2 = __expf(v2); v3 = __expf(v3);
                } else if (z == 2){
                    v0 = 1.f/(1.f+__expf(-v0)); v1 = 1.f/(1.f+__expf(-v1));
                    v2 = 1.f/(1.f+__expf(-v2)); v3 = 1.f/(1.f+__expf(-v3));
                }
                *reinterpret_cast<unsigned*>(CoutH + (size_t)r*Cq + col)     = pack2(v0, v1);
                *reinterpret_cast<unsigned*>(CoutH + (size_t)(r+8)*Cq + col) = pack2(v2, v3);
            } else {
                *reinterpret_cast<float2*>(Cext + (size_t)r*Cq + col)     = make_float2(v0, v1);
                *reinterpret_cast<float2*>(Cext + (size_t)(r+8)*Cq + col) = make_float2(v2, v3);
            }
        }
    }
}

// ================= chunked bi_wkv scan (g_k holds exp(k), fp16) =================
__device__ __forceinline__ float ew_of(float d){
    return __expf(-__expf(d * (1.0f / (float)Tq)));
}

// Phase A: chunk-local sums, 2 channels/thread. grid (Ss, Bq), block 384.
__global__ __launch_bounds__(384) void wkv_chunk(const float* __restrict__ decay)
{
    int s = blockIdx.x, b = blockIdx.y;
    int pr = threadIdx.x;            // pair index 0..383
    float2 dc = *reinterpret_cast<const float2*>(decay + 2*pr);
    float ew0 = ew_of(dc.x), ew1 = ew_of(dc.y);

    size_t base = ((size_t)b*Tq + s*Ls)*Cq + 2*pr;

    float fF0=0.f, dF0=0.f, fB0=0.f, dB0=0.f, pw0=1.f;
    float fF1=0.f, dF1=0.f, fB1=0.f, dB1=0.f, pw1=1.f;
    #pragma unroll
    for (int i=0;i<Ls;i++){
        size_t idx = base + (size_t)i*Cq;
        float2 ek = __half22float2(*reinterpret_cast<const __half2*>(g_k + idx));
        float2 vv = __half22float2(*reinterpret_cast<const __half2*>(g_v + idx));
        fF0 = fmaf(ew0, fF0, ek.x*vv.x);  dF0 = fmaf(ew0, dF0, ek.x);
        fF1 = fmaf(ew1, fF1, ek.y*vv.y);  dF1 = fmaf(ew1, dF1, ek.y);
        fB0 = fmaf(pw0, ek.x*vv.x, fB0);  dB0 = fmaf(pw0, ek.x, dB0);
        fB1 = fmaf(pw1, ek.y*vv.y, fB1);  dB1 = fmaf(pw1, ek.y, dB1);
        pw0 *= ew0; pw1 *= ew1;
    }
    size_t ci = ((size_t)b*Ss + s)*(Cq/2) + pr;
    g_cFP[ci] = make_float4(fF0, dF0, fF1, dF1);
    g_cBP[ci] = make_float4(fB0, dB0, fB1, dB1);
}

// Phase B: carry scan per channel-pair. gridDim.y = direction.
__global__ __launch_bounds__(256) void wkv_carry(const float* __restrict__ decay)
{
    int p = blockIdx.x * blockDim.x + threadIdx.x;
    if (p >= NBC/2) return;
    int b = p / (Cq/2), pr = p % (Cq/2);
    float2 dc = *reinterpret_cast<const float2*>(decay + 2*pr);
    float ew0 = ew_of(dc.x), ew1 = ew_of(dc.y);
    float a0 = ew0*ew0; a0*=a0; a0*=a0; a0*=a0;   // ew0^16
    float a1 = ew1*ew1; a1*=a1; a1*=a1; a1*=a1;   // ew1^16
    size_t base = (size_t)b*Ss*(Cq/2) + pr;

    if (blockIdx.y == 0){
        float4 st = make_float4(0,0,0,0);
        #pragma unroll 8
        for (int s=0;s<Ss;s++){
            size_t ci = base + (size_t)s*(Cq/2);
            float4 cf = g_cFP[ci];
            g_FiP[ci] = st;
            st.x = fmaf(a0, st.x, cf.x);  st.y = fmaf(a0, st.y, cf.y);
            st.z = fmaf(a1, st.z, cf.z);  st.w = fmaf(a1, st.w, cf.w);
        }
    } else {
        float4 st = make_float4(0,0,0,0);
        #pragma unroll 8
        for (int s=Ss-1;s>=0;s--){
            size_t ci = base + (size_t)s*(Cq/2);
            float4 cb = g_cBP[ci];
            g_BiP[ci] = st;
            st.x = fmaf(a0, st.x, cb.x);  st.y = fmaf(a0, st.y, cb.y);
            st.z = fmaf(a1, st.z, cb.z);  st.w = fmaf(a1, st.w, cb.w);
        }
    }
}

// Phase C: apply carries, 2 channels/thread. grid (Ss, Bq*3), block 128.
__global__ __launch_bounds__(128) void wkv_apply(const float* __restrict__ decay,
                                                 const float* __restrict__ first)
{
    int s = blockIdx.x;
    int b = blockIdx.y / 3;
    int pr = (blockIdx.y % 3)*128 + threadIdx.x;   // pair index 0..383
    float2 dc = *reinterpret_cast<const float2*>(decay + 2*pr);
    float2 fu = *reinterpret_cast<const float2*>(first + 2*pr);
    float ew0 = ew_of(dc.x), ew1 = ew_of(dc.y);
    float eu0 = __expf(fu.x * (1.0f/(float)Tq));
    float eu1 = __expf(fu.y * (1.0f/(float)Tq));

    size_t base = ((size_t)b*Tq + s*Ls)*Cq + 2*pr;
    size_t ci   = ((size_t)b*Ss + s)*(Cq/2) + pr;

    // backward micro-scan (exclusive per element)
    float bn0A[Ls], bd0A[Ls], bn1A[Ls], bd1A[Ls];
    float4 bi = g_BiP[ci];
    float bn0 = bi.x, bd0 = bi.y, bn1 = bi.z, bd1 = bi.w;
    #pragma unroll
    for (int i=Ls-1;i>=0;i--){
        size_t idx = base + (size_t)i*Cq;
        float2 ek = __half22float2(*reinterpret_cast<const __half2*>(g_k + idx));
        float2 vv = __half22float2(*reinterpret_cast<const __half2*>(g_v + idx));
        bn0A[i] = bn0; bd0A[i] = bd0;
        bn1A[i] = bn1; bd1A[i] = bd1;
        bn0 = fmaf(ew0, bn0, ek.x*vv.x);  bd0 = fmaf(ew0, bd0, ek.x);
        bn1 = fmaf(ew1, bn1, ek.y*vv.y);  bd1 = fmaf(ew1, bd1, ek.y);
    }

    // forward micro-scan + combine + sr multiply
    float4 fi = g_FiP[ci];
    float fn0 = fi.x, fd0 = fi.y, fn1 = fi.z, fd1 = fi.w;
    #pragma unroll
    for (int i=0;i<Ls;i++){
        size_t idx = base + (size_t)i*Cq;
        float2 ek = __half22float2(*reinterpret_cast<const __half2*>(g_k + idx));
        float2 vv = __half22float2(*reinterpret_cast<const __half2*>(g_v + idx));
        float2 sr = __half22float2(*reinterpret_cast<const __half2*>(g_sr + idx));
        float e0 = eu0 * ek.x, e1 = eu1 * ek.y;
        float o0 = (fn0 + bn0A[i] + e0*vv.x) / (fd0 + bd0A[i] + e0);
        float o1 = (fn1 + bn1A[i] + e1*vv.y) / (fd1 + bd1A[i] + e1);
        *reinterpret_cast<__half2*>(g_y + idx) = __floats2half2_rn(sr.x*o0, sr.y*o1);
        fn0 = fmaf(ew0, fn0, ek.x*vv.x);  fd0 = fmaf(ew0, fd0, ek.x);
        fn1 = fmaf(ew1, fn1, ek.y*vv.y);  fd1 = fmaf(ew1, fd1, ek.y);
    }
}

extern "C" void kernel_launch(void* const* d_in, const int* in_sizes, int n_in,
                              void* d_out, int out_size)
{
    const float* x       = (const float*)d_in[0];
    const float* key_w   = (const float*)d_in[1];
    const float* value_w = (const float*)d_in[2];
    const float* recep_w = (const float*)d_in[3];
    const float* out_w   = (const float*)d_in[4];
    const float* decay   = (const float*)d_in[5];
    const float* first   = (const float*)d_in[6];
    const float* mk      = (const float*)d_in[7];
    const float* mv      = (const float*)d_in[8];
    const float* mr      = (const float*)d_in[9];
    float* out = (float*)d_out;

    // 0) prep: weights to fp16; premix xk/xv/xr to fp16
    prep_w<<<(WN+255)/256, 256>>>(key_w, value_w, recep_w, out_w);
    prep_a<<<(Mq*(Cq/4))/256, 256>>>(x, mk, mv, mr);

    // 1) exp(k), v, sr  (pure-async fp16 GEMMs)
    dim3 grid1(Cq/BN, Mq/BM, 3);
    gemm_fp16<true><<<grid1, 256>>>(nullptr);

    // 2) chunked bidirectional scan
    wkv_chunk<<<dim3(Ss, Bq), 384>>>(decay);
    wkv_carry<<<dim3((NBC/2 + 255)/256, 2), 256>>>(decay);
    wkv_apply<<<dim3(Ss, Bq*3), 128>>>(decay, first);

    // 3) out = y @ output_w^T
    dim3 grid2(Cq/BN, Mq/BM, 1);
    gemm_fp16<false><<<grid2, 256>>>(out);
}

// round 17
// speedup vs baseline: 2.1918x; 1.0050x over previous
#include <cuda_runtime.h>
#include <cuda_fp16.h>
#include <cstdint>

// Problem constants
#define Bq 16
#define Tq 1024
#define Cq 768
#define Mq (Bq*Tq)          // 16384
#define NBC (Bq*Cq)         // 12288
#define Ls 16               // chunk length
#define Ss 64               // num chunks (Ls*Ss == Tq)
#define WN (Cq*Cq)          // 589824 weight elements
#define ASZ 12582912        // Mq*Cq
#define CPAIR (Bq*Ss*(Cq/2))   // channel-pair carry count

// -------- device scratch (static, no allocations) --------
__device__ __half g_xm[3*ASZ];     // premixed A matrices: xk, xv, xr (fp16)
__device__ __half g_k [ASZ];       // exp(k), fp16
__device__ __half g_v [ASZ];       // v, fp16
__device__ __half g_sr[ASZ];       // sigmoid(r), fp16
__device__ __half g_y [ASZ];       // sr*wkv, fp16 (A of final GEMM)
__device__ __half g_wh[4*WN];      // fp16 weights: k,v,r,o
// carries packed per channel-pair: (num0, den0, num1, den1), fp32
__device__ float4 g_cFP[CPAIR];
__device__ float4 g_cBP[CPAIR];
__device__ float4 g_FiP[CPAIR];
__device__ float4 g_BiP[CPAIR];

// -------- helpers --------
__device__ __forceinline__ void cp_async16(uint32_t smem_dst, const void* gmem_src){
    asm volatile("cp.async.cg.shared.global [%0], [%1], 16;\n" :: "r"(smem_dst), "l"(gmem_src));
}
#define CP_COMMIT() asm volatile("cp.async.commit_group;\n" ::: "memory")
#define CP_WAIT0()  asm volatile("cp.async.wait_group 0;\n" ::: "memory")

__device__ __forceinline__ void ldmx4(unsigned &r0, unsigned &r1, unsigned &r2, unsigned &r3,
                                      uint32_t addr){
    asm volatile("ldmatrix.sync.aligned.m8n8.x4.shared.b16 {%0,%1,%2,%3}, [%4];"
      : "=r"(r0), "=r"(r1), "=r"(r2), "=r"(r3) : "r"(addr));
}

__device__ __forceinline__ void mma16(float d[4], const unsigned a[4], const unsigned b[2]){
    asm volatile(
      "mma.sync.aligned.m16n8k16.row.col.f32.f16.f16.f32 "
      "{%0,%1,%2,%3}, {%4,%5,%6,%7}, {%8,%9}, {%0,%1,%2,%3};\n"
      : "+f"(d[0]), "+f"(d[1]), "+f"(d[2]), "+f"(d[3])
      : "r"(a[0]), "r"(a[1]), "r"(a[2]), "r"(a[3]), "r"(b[0]), "r"(b[1]));
}

__device__ __forceinline__ unsigned pack2(float a, float b){
    __half2 h = __floats2half2_rn(a, b);
    return *reinterpret_cast<unsigned*>(&h);
}

// -------- weight prep: convert all 4 weight matrices to fp16 --------
__global__ void prep_w(const float* __restrict__ wk, const float* __restrict__ wv,
                       const float* __restrict__ wr, const float* __restrict__ wo)
{
    int i = blockIdx.x * blockDim.x + threadIdx.x;
    if (i >= WN) return;
    g_wh[i       ] = __float2half_rn(wk[i]);
    g_wh[i +   WN] = __float2half_rn(wv[i]);
    g_wh[i + 2*WN] = __float2half_rn(wr[i]);
    g_wh[i + 3*WN] = __float2half_rn(wo[i]);
}

// -------- A prep: q_shift + token mix for all 3 variants, fp16 output --------
__global__ __launch_bounds__(256) void prep_a(
    const float* __restrict__ x,
    const float* __restrict__ mk, const float* __restrict__ mv, const float* __restrict__ mr)
{
    int i = blockIdx.x * blockDim.x + threadIdx.x;   // group of 4 channels
    int m  = i / (Cq/4);
    int kk = (i % (Cq/4)) * 4;

    int t  = m & (Tq-1);
    int bb = m >> 10;
    int grp = kk / 192;
    int wq = t & 31, hq = t >> 5;
    int tt; bool valid;
    if      (grp==0) { tt = t-1;  valid = (wq > 0);  }
    else if (grp==1) { tt = t+1;  valid = (wq < 31); }
    else if (grp==2) { tt = t-32; valid = (hq > 0);  }
    else             { tt = t+32; valid = (hq < 31); }

    float4 xv = *reinterpret_cast<const float4*>(x + (size_t)m*Cq + kk);
    float4 xs = make_float4(0.f,0.f,0.f,0.f);
    if (valid)
        xs = *reinterpret_cast<const float4*>(x + ((size_t)(bb<<10) + tt)*Cq + kk);

    size_t off = (size_t)m*Cq + kk;
    const float* mixes[3] = {mk, mv, mr};
    #pragma unroll
    for (int z=0; z<3; z++){
        float4 mx = *reinterpret_cast<const float4*>(mixes[z] + kk);
        float a0 = mx.x*(xv.x - xs.x) + xs.x;
        float a1 = mx.y*(xv.y - xs.y) + xs.y;
        float a2 = mx.z*(xv.z - xs.z) + xs.z;
        float a3 = mx.w*(xv.w - xs.w) + xs.w;
        *reinterpret_cast<uint2*>(g_xm + (size_t)z*ASZ + off) =
            make_uint2(pack2(a0, a1), pack2(a2, a3));
    }
}

// -------- GEMM: C[m,n] = sum_k A[m,k] * W[n,k], fp16 m16n8k16, pure cp.async --------
#define BM 128
#define BN 128
#define BK 32
#define NKI (Cq/BK)     // 24
#define PITCH 40        // halfs per row (80B)
#define TILE_H (BM*PITCH)
#define PITCH2 136      // epilogue staging pitch (halfs): banks (68r+c4)%32 all distinct

template<bool MIXED>
__global__ __launch_bounds__(256, 2) void gemm_fp16(float* __restrict__ Cext)
{
    __shared__ __align__(16) char smem_raw[4*TILE_H*2];   // 40960 B
    __half* smAB = reinterpret_cast<__half*>(smem_raw);   // [4*TILE_H]: A0,A1,B0,B1
    __half* smE  = reinterpret_cast<__half*>(smem_raw);   // epilogue staging (128*PITCH2=34816B)

    int z = MIXED ? blockIdx.z : 0;
    const __half* W    = g_wh + (size_t)(MIXED ? z : 3)*WN;
    const __half* Asrc = MIXED ? (g_xm + (size_t)z*ASZ) : g_y;
    __half* CoutH = nullptr;
    if (MIXED) CoutH = (z==0) ? g_k : (z==1) ? g_v : g_sr;

    const int m0 = blockIdx.y * BM;
    const int n0 = blockIdx.x * BN;
    const int tid  = threadIdx.x;
    const int lane = tid & 31;
    const int wid  = tid >> 5;
    const int wm = wid & 3;
    const int wn = wid >> 2;
    const int grp8 = lane >> 2;
    const int c4   = lane & 3;

    const uint32_t uA = (uint32_t)__cvta_generic_to_shared(smAB);
    const uint32_t uB = uA + (uint32_t)(2*TILE_H*2);

    const int q = lane >> 3, rr = lane & 7;
    const uint32_t aOff = (uint32_t)((wm*32 + ((q&1)<<3) + rr)*80 + (q>>1)*16);
    const uint32_t bOff = (uint32_t)((wn*64 + ((q>>1)<<3) + rr)*80 + (q&1)*16);

    auto loadA = [&](int buf, int kt){
        uint32_t base = uA + buf*(TILE_H*2);
        #pragma unroll
        for (int p=0;p<2;p++){
            int linear = p*256 + tid;
            int row = linear >> 2, seg = linear & 3;
            cp_async16(base + (uint32_t)(row*80 + seg*16),
                       Asrc + (size_t)(m0+row)*Cq + kt + seg*8);
        }
    };
    auto loadB = [&](int buf, int kt){
        uint32_t base = uB + buf*(TILE_H*2);
        #pragma unroll
        for (int p=0;p<2;p++){
            int linear = p*256 + tid;
            int row = linear >> 2, seg = linear & 3;
            cp_async16(base + (uint32_t)(row*80 + seg*16),
                       W + (size_t)(n0+row)*Cq + kt + seg*8);
        }
    };

    float acc[2][8][4];
    #pragma unroll
    for (int i=0;i<2;i++)
      #pragma unroll
      for (int j=0;j<8;j++)
        #pragma unroll
        for (int qd=0;qd<4;qd++) acc[i][j][qd] = 0.f;

    // prologue
    loadA(0, 0); loadB(0, 0); CP_COMMIT();
    CP_WAIT0();
    __syncthreads();

    for (int it = 0; it < NKI; it++){
        int cur = it & 1;
        if (it + 1 < NKI){
            loadA(cur^1, (it+1)*BK);
            loadB(cur^1, (it+1)*BK);
            CP_COMMIT();
        }

        uint32_t aBuf = uA + cur*(TILE_H*2);
        uint32_t bBuf = uB + cur*(TILE_H*2);
        #pragma unroll
        for (int ks=0; ks<2; ks++){
            unsigned afr[2][4];
            #pragma unroll
            for (int i=0;i<2;i++)
                ldmx4(afr[i][0], afr[i][1], afr[i][2], afr[i][3],
                      aBuf + aOff + (uint32_t)(i*1280 + ks*32));
            unsigned bfr[8][2];
            #pragma unroll
            for (int jp=0;jp<4;jp++)
                ldmx4(bfr[2*jp][0], bfr[2*jp][1], bfr[2*jp+1][0], bfr[2*jp+1][1],
                      bBuf + bOff + (uint32_t)(jp*1280 + ks*32));
            #pragma unroll
            for (int i=0;i<2;i++)
                #pragma unroll
                for (int j=0;j<8;j++)
                    mma16(acc[i][j], afr[i], bfr[j]);
        }

        if (it + 1 < NKI) CP_WAIT0();
        __syncthreads();
    }

    // ---- epilogue ----
    if (MIXED){
        // stage in smem (bank-conflict-free PITCH2), then coalesced 16B stores
        #pragma unroll
        for (int i=0;i<2;i++){
            int rl = wm*32 + i*16 + grp8;
            #pragma unroll
            for (int j=0;j<8;j++){
                int col = wn*64 + j*8 + 2*c4;
                float v0 = acc[i][j][0], v1 = acc[i][j][1];
                float v2 = acc[i][j][2], v3 = acc[i][j][3];
                if (z == 0){
                    v0 = __expf(v0); v1 = __expf(v1);
                    v2 = __expf(v2); v3 = __expf(v3);
                } else if (z == 2){
                    v0 = 1.f/(1.f+__expf(-v0)); v1 = 1.f/(1.f+__expf(-v1));
                    v2 = 1.f/(1.f+__expf(-v2)); v3 = 1.f/(1.f+__expf(-v3));
                }
                *reinterpret_cast<unsigned*>(smE + rl*PITCH2 + col)     = pack2(v0, v1);
                *reinterpret_cast<unsigned*>(smE + (rl+8)*PITCH2 + col) = pack2(v2, v3);
            }
        }
        __syncthreads();
        #pragma unroll
        for (int p=0;p<8;p++){
            int linear = p*256 + tid;
            int row = linear >> 4, u = linear & 15;
            uint4 val = *reinterpret_cast<const uint4*>(smE + row*PITCH2 + u*8);
            *reinterpret_cast<uint4*>(CoutH + (size_t)(m0+row)*Cq + n0 + u*8) = val;
        }
    } else {
        #pragma unroll
        for (int i=0;i<2;i++){
            int r = m0 + wm*32 + i*16 + grp8;
            #pragma unroll
            for (int j=0;j<8;j++){
                int col = n0 + wn*64 + j*8 + 2*c4;
                *reinterpret_cast<float2*>(Cext + (size_t)r*Cq + col)     = make_float2(acc[i][j][0], acc[i][j][1]);
                *reinterpret_cast<float2*>(Cext + (size_t)(r+8)*Cq + col) = make_float2(acc[i][j][2], acc[i][j][3]);
            }
        }
    }
}

// ================= chunked bi_wkv scan (g_k holds exp(k), fp16) =================
__device__ __forceinline__ float ew_of(float d){
    return __expf(-__expf(d * (1.0f / (float)Tq)));
}

// Phase A: chunk-local sums, 2 channels/thread. grid (Ss, Bq), block 384.
__global__ __launch_bounds__(384) void wkv_chunk(const float* __restrict__ decay)
{
    int s = blockIdx.x, b = blockIdx.y;
    int pr = threadIdx.x;            // pair index 0..383
    float2 dc = *reinterpret_cast<const float2*>(decay + 2*pr);
    float ew0 = ew_of(dc.x), ew1 = ew_of(dc.y);

    size_t base = ((size_t)b*Tq + s*Ls)*Cq + 2*pr;

    float fF0=0.f, dF0=0.f, fB0=0.f, dB0=0.f, pw0=1.f;
    float fF1=0.f, dF1=0.f, fB1=0.f, dB1=0.f, pw1=1.f;
    #pragma unroll
    for (int i=0;i<Ls;i++){
        size_t idx = base + (size_t)i*Cq;
        float2 ek = __half22float2(*reinterpret_cast<const __half2*>(g_k + idx));
        float2 vv = __half22float2(*reinterpret_cast<const __half2*>(g_v + idx));
        fF0 = fmaf(ew0, fF0, ek.x*vv.x);  dF0 = fmaf(ew0, dF0, ek.x);
        fF1 = fmaf(ew1, fF1, ek.y*vv.y);  dF1 = fmaf(ew1, dF1, ek.y);
        fB0 = fmaf(pw0, ek.x*vv.x, fB0);  dB0 = fmaf(pw0, ek.x, dB0);
        fB1 = fmaf(pw1, ek.y*vv.y, fB1);  dB1 = fmaf(pw1, ek.y, dB1);
        pw0 *= ew0; pw1 *= ew1;
    }
    size_t ci = ((size_t)b*Ss + s)*(Cq/2) + pr;
    g_cFP[ci] = make_float4(fF0, dF0, fF1, dF1);
    g_cBP[ci] = make_float4(fB0, dB0, fB1, dB1);
}

// Phase B: carry scan per channel-pair. gridDim.y = direction.
__global__ __launch_bounds__(256) void wkv_carry(const float* __restrict__ decay)
{
    int p = blockIdx.x * blockDim.x + threadIdx.x;
    if (p >= NBC/2) return;
    int b = p / (Cq/2), pr = p % (Cq/2);
    float2 dc = *reinterpret_cast<const float2*>(decay + 2*pr);
    float ew0 = ew_of(dc.x), ew1 = ew_of(dc.y);
    float a0 = ew0*ew0; a0*=a0; a0*=a0; a0*=a0;   // ew0^16
    float a1 = ew1*ew1; a1*=a1; a1*=a1; a1*=a1;   // ew1^16
    size_t base = (size_t)b*Ss*(Cq/2) + pr;

    if (blockIdx.y == 0){
        float4 st = make_float4(0,0,0,0);
        #pragma unroll 8
        for (int s=0;s<Ss;s++){
            size_t ci = base + (size_t)s*(Cq/2);
            float4 cf = g_cFP[ci];
            g_FiP[ci] = st;
            st.x = fmaf(a0, st.x, cf.x);  st.y = fmaf(a0, st.y, cf.y);
            st.z = fmaf(a1, st.z, cf.z);  st.w = fmaf(a1, st.w, cf.w);
        }
    } else {
        float4 st = make_float4(0,0,0,0);
        #pragma unroll 8
        for (int s=Ss-1;s>=0;s--){
            size_t ci = base + (size_t)s*(Cq/2);
            float4 cb = g_cBP[ci];
            g_BiP[ci] = st;
            st.x = fmaf(a0, st.x, cb.x);  st.y = fmaf(a0, st.y, cb.y);
            st.z = fmaf(a1, st.z, cb.z);  st.w = fmaf(a1, st.w, cb.w);
        }
    }
}

// Phase C: apply carries, 2 channels/thread. grid (Ss, Bq*3), block 128.
__global__ __launch_bounds__(128) void wkv_apply(const float* __restrict__ decay,
                                                 const float* __restrict__ first)
{
    int s = blockIdx.x;
    int b = blockIdx.y / 3;
    int pr = (blockIdx.y % 3)*128 + threadIdx.x;   // pair index 0..383
    float2 dc = *reinterpret_cast<const float2*>(decay + 2*pr);
    float2 fu = *reinterpret_cast<const float2*>(first + 2*pr);
    float ew0 = ew_of(dc.x), ew1 = ew_of(dc.y);
    float eu0 = __expf(fu.x * (1.0f/(float)Tq));
    float eu1 = __expf(fu.y * (1.0f/(float)Tq));

    size_t base = ((size_t)b*Tq + s*Ls)*Cq + 2*pr;
    size_t ci   = ((size_t)b*Ss + s)*(Cq/2) + pr;

    // backward micro-scan (exclusive per element)
    float bn0A[Ls], bd0A[Ls], bn1A[Ls], bd1A[Ls];
    float4 bi = g_BiP[ci];
    float bn0 = bi.x, bd0 = bi.y, bn1 = bi.z, bd1 = bi.w;
    #pragma unroll
    for (int i=Ls-1;i>=0;i--){
        size_t idx = base + (size_t)i*Cq;
        float2 ek = __half22float2(*reinterpret_cast<const __half2*>(g_k + idx));
        float2 vv = __half22float2(*reinterpret_cast<const __half2*>(g_v + idx));
        bn0A[i] = bn0; bd0A[i] = bd0;
        bn1A[i] = bn1; bd1A[i] = bd1;
        bn0 = fmaf(ew0, bn0, ek.x*vv.x);  bd0 = fmaf(ew0, bd0, ek.x);
        bn1 = fmaf(ew1, bn1, ek.y*vv.y);  bd1 = fmaf(ew1, bd1, ek.y);
    }

    // forward micro-scan + combine + sr multiply
    float4 fi = g_FiP[ci];
    float fn0 = fi.x, fd0 = fi.y, fn1 = fi.z, fd1 = fi.w;
    #pragma unroll
    for (int i=0;i<Ls;i++){
        size_t idx = base + (size_t)i*Cq;
        float2 ek = __half22float2(*reinterpret_cast<const __half2*>(g_k + idx));
        float2 vv = __half22float2(*reinterpret_cast<const __half2*>(g_v + idx));
        float2 sr = __half22float2(*reinterpret_cast<const __half2*>(g_sr + idx));
        float e0 = eu0 * ek.x, e1 = eu1 * ek.y;
        float o0 = (fn0 + bn0A[i] + e0*vv.x) / (fd0 + bd0A[i] + e0);
        float o1 = (fn1 + bn1A[i] + e1*vv.y) / (fd1 + bd1A[i] + e1);
        *reinterpret_cast<__half2*>(g_y + idx) = __floats2half2_rn(sr.x*o0, sr.y*o1);
        fn0 = fmaf(ew0, fn0, ek.x*vv.x);  fd0 = fmaf(ew0, fd0, ek.x);
        fn1 = fmaf(ew1, fn1, ek.y*vv.y);  fd1 = fmaf(ew1, fd1, ek.y);
    }
}

extern "C" void kernel_launch(void* const* d_in, const int* in_sizes, int n_in,
                              void* d_out, int out_size)
{
    const float* x       = (const float*)d_in[0];
    const float* key_w   = (const float*)d_in[1];
    const float* value_w = (const float*)d_in[2];
    const float* recep_w = (const float*)d_in[3];
    const float* out_w   = (const float*)d_in[4];
    const float* decay   = (const float*)d_in[5];
    const float* first   = (const float*)d_in[6];
    const float* mk      = (const float*)d_in[7];
    const float* mv      = (const float*)d_in[8];
    const float* mr      = (const float*)d_in[9];
    float* out = (float*)d_out;

    // 0) prep: weights to fp16; premix xk/xv/xr to fp16
    prep_w<<<(WN+255)/256, 256>>>(key_w, value_w, recep_w, out_w);
    prep_a<<<(Mq*(Cq/4))/256, 256>>>(x, mk, mv, mr);

    // 1) exp(k), v, sr  (pure-async fp16 GEMMs, staged epilogue)
    dim3 grid1(Cq/BN, Mq/BM, 3);
    gemm_fp16<true><<<grid1, 256>>>(nullptr);

    // 2) chunked bidirectional scan
    wkv_chunk<<<dim3(Ss, Bq), 384>>>(decay);
    wkv_carry<<<dim3((NBC/2 + 255)/256, 2), 256>>>(decay);
    wkv_apply<<<dim3(Ss, Bq*3), 128>>>(decay, first);

    // 3) out = y @ output_w^T
    dim3 grid2(Cq/BN, Mq/BM, 1);
    gemm_fp16<false><<<grid2, 256>>>(out);
}